// round 1
// baseline (speedup 1.0000x reference)
#include <cuda_runtime.h>
#include <cuda_bf16.h>
#include <float.h>
#include <stdint.h>

// Problem dims (fixed by setup_inputs)
#define NN   4096
#define FF   512
#define WRDS (NN / 32)   // 128 words per bitset row
#define MAX_HOP_LAUNCH 6

// ---------------- device scratch (no allocations allowed) ----------------
__device__ float    g_Wh[NN * FF];
__device__ float    g_Wa[NN * FF];
__device__ float    g_hk[NN * FF];
__device__ float    g_src[NN];
__device__ float    g_dst[NN];
__device__ unsigned g_Abits[NN * WRDS];
__device__ unsigned g_P[NN * WRDS];
__device__ unsigned g_Q[NN * WRDS];
__device__ float    g_S[(size_t)NN * NN];   // 64 MB scores / att2

// ---------------- helpers ----------------
__device__ __forceinline__ float gelu_tanh(float x) {
    // jax.nn.gelu default (approximate=True)
    float x3 = x * x * x;
    return 0.5f * x * (1.0f + tanhf(0.7978845608028654f * (x + 0.044715f * x3)));
}

// ============================================================
// GEMM NT: C[M,N] = A[M,K] * B[N,K]^T   (both K-contiguous, row-major)
// 128x128 tile, BK=8, 256 threads, 8x8 per thread.
// Optional epilogue: apply reachability mask (masked -> -FLT_MAX).
// M,N,K must be multiples of 128/128/8 (they are here).
// ============================================================
template <bool MASKED>
__global__ void __launch_bounds__(256) gemm_nt_kernel(
    const float* __restrict__ A, const float* __restrict__ B,
    float* __restrict__ C, int M, int N, int K,
    const unsigned* __restrict__ maskbits)
{
    __shared__ __align__(16) float As[8][128];
    __shared__ __align__(16) float Bs[8][128];

    const int tid = threadIdx.x;
    const int bx = blockIdx.x;   // N tile
    const int by = blockIdx.y;   // M tile

    const int lr = tid >> 1;          // 0..127 row within tile
    const int lk = (tid & 1) * 4;     // 0 or 4

    const float* Aptr = A + (size_t)(by * 128 + lr) * K + lk;
    const float* Bptr = B + (size_t)(bx * 128 + lr) * K + lk;

    const int tx = tid & 15;          // 0..15 -> 8 cols each
    const int ty = tid >> 4;          // 0..15 -> 8 rows each

    float acc[8][8];
#pragma unroll
    for (int i = 0; i < 8; i++)
#pragma unroll
        for (int j = 0; j < 8; j++) acc[i][j] = 0.0f;

    for (int k0 = 0; k0 < K; k0 += 8) {
        float4 a4 = *reinterpret_cast<const float4*>(Aptr + k0);
        float4 b4 = *reinterpret_cast<const float4*>(Bptr + k0);
        __syncthreads();
        As[lk + 0][lr] = a4.x; As[lk + 1][lr] = a4.y;
        As[lk + 2][lr] = a4.z; As[lk + 3][lr] = a4.w;
        Bs[lk + 0][lr] = b4.x; Bs[lk + 1][lr] = b4.y;
        Bs[lk + 2][lr] = b4.z; Bs[lk + 3][lr] = b4.w;
        __syncthreads();
#pragma unroll
        for (int kk = 0; kk < 8; kk++) {
            float ar[8], br[8];
            float4 av0 = *reinterpret_cast<const float4*>(&As[kk][ty * 8]);
            float4 av1 = *reinterpret_cast<const float4*>(&As[kk][ty * 8 + 4]);
            float4 bv0 = *reinterpret_cast<const float4*>(&Bs[kk][tx * 8]);
            float4 bv1 = *reinterpret_cast<const float4*>(&Bs[kk][tx * 8 + 4]);
            ar[0]=av0.x; ar[1]=av0.y; ar[2]=av0.z; ar[3]=av0.w;
            ar[4]=av1.x; ar[5]=av1.y; ar[6]=av1.z; ar[7]=av1.w;
            br[0]=bv0.x; br[1]=bv0.y; br[2]=bv0.z; br[3]=bv0.w;
            br[4]=bv1.x; br[5]=bv1.y; br[6]=bv1.z; br[7]=bv1.w;
#pragma unroll
            for (int i = 0; i < 8; i++)
#pragma unroll
                for (int j = 0; j < 8; j++)
                    acc[i][j] = fmaf(ar[i], br[j], acc[i][j]);
        }
    }

#pragma unroll
    for (int i = 0; i < 8; i++) {
        int row = by * 128 + ty * 8 + i;
#pragma unroll
        for (int j = 0; j < 8; j++) {
            int col = bx * 128 + tx * 8 + j;
            float v = acc[i][j];
            if (MASKED) {
                unsigned w = maskbits[(size_t)row * (N / 32) + (col >> 5)];
                if (!((w >> (col & 31)) & 1u)) v = -FLT_MAX;
            }
            C[(size_t)row * N + col] = v;
        }
    }
}

// ============================================================
// GEMM NN: C[M,N] = A[M,K] * B[K,N]    (row-major)
// ============================================================
__global__ void __launch_bounds__(256) gemm_nn_kernel(
    const float* __restrict__ A, const float* __restrict__ B,
    float* __restrict__ C, int M, int N, int K)
{
    __shared__ __align__(16) float As[8][128];
    __shared__ __align__(16) float Bs[8][128];

    const int tid = threadIdx.x;
    const int bx = blockIdx.x;   // N tile
    const int by = blockIdx.y;   // M tile

    const int lr = tid >> 1;
    const int lk = (tid & 1) * 4;
    const float* Aptr = A + (size_t)(by * 128 + lr) * K + lk;

    const int kr = tid >> 5;              // 0..7
    const int nc = (tid & 31) * 4;        // 0..124
    const float* Bptr = B + (size_t)kr * N + bx * 128 + nc;

    const int tx = tid & 15;
    const int ty = tid >> 4;

    float acc[8][8];
#pragma unroll
    for (int i = 0; i < 8; i++)
#pragma unroll
        for (int j = 0; j < 8; j++) acc[i][j] = 0.0f;

    for (int k0 = 0; k0 < K; k0 += 8) {
        float4 a4 = *reinterpret_cast<const float4*>(Aptr + k0);
        float4 b4 = *reinterpret_cast<const float4*>(Bptr + (size_t)k0 * N);
        __syncthreads();
        As[lk + 0][lr] = a4.x; As[lk + 1][lr] = a4.y;
        As[lk + 2][lr] = a4.z; As[lk + 3][lr] = a4.w;
        *reinterpret_cast<float4*>(&Bs[kr][nc]) = b4;
        __syncthreads();
#pragma unroll
        for (int kk = 0; kk < 8; kk++) {
            float ar[8], br[8];
            float4 av0 = *reinterpret_cast<const float4*>(&As[kk][ty * 8]);
            float4 av1 = *reinterpret_cast<const float4*>(&As[kk][ty * 8 + 4]);
            float4 bv0 = *reinterpret_cast<const float4*>(&Bs[kk][tx * 8]);
            float4 bv1 = *reinterpret_cast<const float4*>(&Bs[kk][tx * 8 + 4]);
            ar[0]=av0.x; ar[1]=av0.y; ar[2]=av0.z; ar[3]=av0.w;
            ar[4]=av1.x; ar[5]=av1.y; ar[6]=av1.z; ar[7]=av1.w;
            br[0]=bv0.x; br[1]=bv0.y; br[2]=bv0.z; br[3]=bv0.w;
            br[4]=bv1.x; br[5]=bv1.y; br[6]=bv1.z; br[7]=bv1.w;
#pragma unroll
            for (int i = 0; i < 8; i++)
#pragma unroll
                for (int j = 0; j < 8; j++)
                    acc[i][j] = fmaf(ar[i], br[j], acc[i][j]);
        }
    }

#pragma unroll
    for (int i = 0; i < 8; i++) {
        int row = by * 128 + ty * 8 + i;
#pragma unroll
        for (int j = 0; j < 8; j++) {
            int col = bx * 128 + tx * 8 + j;
            C[(size_t)row * N + col] = acc[i][j];
        }
    }
}

// ============================================================
// Build bit-packed adjacency: one block per row, one thread per 32-col word.
// ============================================================
__global__ void build_bits_kernel(const float* __restrict__ A, unsigned* __restrict__ bits)
{
    int i = blockIdx.x;
    int w = threadIdx.x;          // 0..127
    const float* row = A + (size_t)i * NN + w * 32;
    unsigned v = 0;
#pragma unroll
    for (int b = 0; b < 32; b++)
        if (row[b] != 0.0f) v |= (1u << b);
    bits[i * WRDS + w] = v;
}

// ============================================================
// src[i] = Wh[i,:].r[0:F],  dst[i] = Wh[i,:].r[F:2F]   (one warp / row)
// ============================================================
__global__ void src_dst_kernel(const float* __restrict__ Wh, const float* __restrict__ r,
                               float* __restrict__ src, float* __restrict__ dst)
{
    int warp = (blockIdx.x * blockDim.x + threadIdx.x) >> 5;
    int lane = threadIdx.x & 31;
    if (warp >= NN) return;
    const float* row = Wh + (size_t)warp * FF;
    float a = 0.f, b = 0.f;
    for (int f = lane; f < FF; f += 32) {
        float v = row[f];
        a = fmaf(v, r[f], a);
        b = fmaf(v, r[FF + f], b);
    }
#pragma unroll
    for (int s = 16; s > 0; s >>= 1) {
        a += __shfl_xor_sync(0xffffffffu, a, s);
        b += __shfl_xor_sync(0xffffffffu, b, s);
    }
    if (lane == 0) { src[warp] = a; dst[warp] = b; }
}

// ============================================================
// Short-distance attention (masked by A, ~21 nnz/row) fused:
//   e_ij = leakyrelu(src_i + dst_j), softmax over nnz(A_i),
//   hk_i = gelu( sum_j att_ij * Wh_j )
// One block (256 threads) per row. Deterministic (prefix-scan index build).
// ============================================================
__global__ void __launch_bounds__(256) short_attn_kernel(
    const float* __restrict__ A, const float* __restrict__ Wh,
    const float* __restrict__ src, const float* __restrict__ dst,
    float* __restrict__ hk)
{
    __shared__ int   s_idx[NN];
    __shared__ float s_w[NN];
    __shared__ int   s_scan[256];
    __shared__ float s_red[256];

    const int i   = blockIdx.x;
    const int tid = threadIdx.x;
    const float* Arow = A + (size_t)i * NN;

    // --- deterministic nnz index list: each thread scans 16 contiguous cols ---
    const int base = tid * 16;
    unsigned m16 = 0; int c = 0;
#pragma unroll
    for (int q = 0; q < 16; q++) {
        if (Arow[base + q] != 0.0f) { m16 |= (1u << q); c++; }
    }
    s_scan[tid] = c;
    __syncthreads();
    // inclusive scan (Hillis-Steele)
#pragma unroll
    for (int s = 1; s < 256; s <<= 1) {
        int v = (tid >= s) ? s_scan[tid - s] : 0;
        __syncthreads();
        s_scan[tid] += v;
        __syncthreads();
    }
    int start = s_scan[tid] - c;
    int cnt   = s_scan[255];
    {
        int p = start;
#pragma unroll
        for (int q = 0; q < 16; q++)
            if ((m16 >> q) & 1u) s_idx[p++] = base + q;
    }
    __syncthreads();

    // --- e + max ---
    float si = src[i];
    float lmax = -FLT_MAX;
    for (int p = tid; p < cnt; p += 256) {
        float e = si + dst[s_idx[p]];
        e = (e > 0.f) ? e : 0.2f * e;
        s_w[p] = e;
        lmax = fmaxf(lmax, e);
    }
    s_red[tid] = lmax;
    __syncthreads();
#pragma unroll
    for (int s = 128; s > 0; s >>= 1) {
        if (tid < s) s_red[tid] = fmaxf(s_red[tid], s_red[tid + s]);
        __syncthreads();
    }
    float mx = s_red[0];
    __syncthreads();

    // --- exp + sum ---
    float lsum = 0.f;
    for (int p = tid; p < cnt; p += 256) {
        float w = expf(s_w[p] - mx);
        s_w[p] = w;
        lsum += w;
    }
    s_red[tid] = lsum;
    __syncthreads();
#pragma unroll
    for (int s = 128; s > 0; s >>= 1) {
        if (tid < s) s_red[tid] += s_red[tid + s];
        __syncthreads();
    }
    float inv = 1.0f / s_red[0];
    __syncthreads();

    // --- weighted sum over neighbors; thread owns features tid, tid+256 ---
    float a0 = 0.f, a1 = 0.f;
    for (int p = 0; p < cnt; p++) {
        float w = s_w[p];
        const float* whr = Wh + (size_t)s_idx[p] * FF;
        a0 = fmaf(w, whr[tid],       a0);
        a1 = fmaf(w, whr[tid + 256], a1);
    }
    hk[(size_t)i * FF + tid]       = gelu_tanh(a0 * inv);
    hk[(size_t)i * FF + tid + 256] = gelu_tanh(a1 * inv);
}

// ============================================================
// One boolean hop: dst[i] = OR_{k in N_A(i)} src[k]   (if active)
//                  dst[i] = src[i]                    (copy when iter done)
// One block (128 threads = 128 words) per row.
// ============================================================
__global__ void hop_step_kernel(const unsigned* __restrict__ Abits,
                                const unsigned* __restrict__ src,
                                unsigned* __restrict__ dst,
                                int iter, const int* __restrict__ num_hops)
{
    __shared__ unsigned s_row[WRDS];
    const int i = blockIdx.x;
    const int t = threadIdx.x;
    s_row[t] = Abits[i * WRDS + t];
    __syncthreads();

    if (iter >= (*num_hops) - 1) {
        dst[i * WRDS + t] = src[i * WRDS + t];
        return;
    }
    unsigned acc = 0;
    for (int w = 0; w < WRDS; w++) {
        unsigned bits = s_row[w];
        while (bits) {
            int b = __ffs(bits) - 1;
            bits &= bits - 1;
            int k = w * 32 + b;
            acc |= src[(size_t)k * WRDS + t];
        }
    }
    dst[i * WRDS + t] = acc;
}

// ============================================================
// Row softmax over 4096-wide rows (in place). 256 threads, 16 vals/thread.
// ============================================================
__global__ void __launch_bounds__(256) row_softmax_kernel(float* __restrict__ S)
{
    __shared__ float s_red[256];
    const int i   = blockIdx.x;
    const int tid = threadIdx.x;
    float* row = S + (size_t)i * NN;

    float vals[16];
    float lmax = -FLT_MAX;
#pragma unroll
    for (int p = 0; p < 16; p++) {
        vals[p] = row[tid + p * 256];
        lmax = fmaxf(lmax, vals[p]);
    }
    s_red[tid] = lmax;
    __syncthreads();
#pragma unroll
    for (int s = 128; s > 0; s >>= 1) {
        if (tid < s) s_red[tid] = fmaxf(s_red[tid], s_red[tid + s]);
        __syncthreads();
    }
    float mx = s_red[0];
    __syncthreads();

    float lsum = 0.f;
#pragma unroll
    for (int p = 0; p < 16; p++) {
        float w = expf(vals[p] - mx);
        vals[p] = w;
        lsum += w;
    }
    s_red[tid] = lsum;
    __syncthreads();
#pragma unroll
    for (int s = 128; s > 0; s >>= 1) {
        if (tid < s) s_red[tid] += s_red[tid + s];
        __syncthreads();
    }
    float inv = 1.0f / s_red[0];
#pragma unroll
    for (int p = 0; p < 16; p++)
        row[tid + p * 256] = vals[p] * inv;
}

// ============================================================
// Host launch
// ============================================================
extern "C" void kernel_launch(void* const* d_in, const int* in_sizes, int n_in,
                              void* d_out, int out_size)
{
    const float* X  = (const float*)d_in[0];   // (4096, 512)
    const float* A  = (const float*)d_in[1];   // (4096, 4096)
    const float* Ws = (const float*)d_in[2];   // (512, 512)
    const float* r  = (const float*)d_in[3];   // (1024, 1)
    const float* Wl = (const float*)d_in[4];   // (512, 512)
    const int*   nh = (const int*)d_in[5];     // num_hops scalar
    float* out = (float*)d_out;                // (4096, 512)

    float *Wh, *Wa, *hk, *src, *dst, *S;
    unsigned *Abits, *P, *Q;
    cudaGetSymbolAddress((void**)&Wh,    g_Wh);
    cudaGetSymbolAddress((void**)&Wa,    g_Wa);
    cudaGetSymbolAddress((void**)&hk,    g_hk);
    cudaGetSymbolAddress((void**)&src,   g_src);
    cudaGetSymbolAddress((void**)&dst,   g_dst);
    cudaGetSymbolAddress((void**)&S,     g_S);
    cudaGetSymbolAddress((void**)&Abits, g_Abits);
    cudaGetSymbolAddress((void**)&P,     g_P);
    cudaGetSymbolAddress((void**)&Q,     g_Q);

    // Wh = X * Ws^T ; Wa = X * Wl^T
    gemm_nt_kernel<false><<<dim3(FF / 128, NN / 128), 256>>>(X, Ws, Wh, NN, FF, FF, nullptr);
    gemm_nt_kernel<false><<<dim3(FF / 128, NN / 128), 256>>>(X, Wl, Wa, NN, FF, FF, nullptr);

    // adjacency bitset
    build_bits_kernel<<<NN, WRDS>>>(A, Abits);

    // src/dst projections
    src_dst_kernel<<<NN / 8, 256>>>(Wh, r, src, dst);

    // short attention -> hk
    short_attn_kernel<<<NN, 256>>>(A, Wh, src, dst, hk);

    // multi-hop reachability (boolean): 6 guarded launches, final result in Q
    hop_step_kernel<<<NN, WRDS>>>(Abits, Abits, P, 0, nh);
    hop_step_kernel<<<NN, WRDS>>>(Abits, P, Q, 1, nh);
    hop_step_kernel<<<NN, WRDS>>>(Abits, Q, P, 2, nh);
    hop_step_kernel<<<NN, WRDS>>>(Abits, P, Q, 3, nh);
    hop_step_kernel<<<NN, WRDS>>>(Abits, Q, P, 4, nh);
    hop_step_kernel<<<NN, WRDS>>>(Abits, P, Q, 5, nh);

    // scores = hk * Wa^T with reach mask -> S
    gemm_nt_kernel<true><<<dim3(NN / 128, NN / 128), 256>>>(hk, Wa, S, NN, NN, FF, Q);

    // row softmax in place
    row_softmax_kernel<<<NN, 256>>>(S);

    // ok = att2 * hk -> out
    gemm_nn_kernel<<<dim3(FF / 128, NN / 128), 256>>>(S, hk, out, NN, FF, NN);
}

// round 3
// speedup vs baseline: 2.0444x; 2.0444x over previous
#include <cuda_runtime.h>
#include <cuda_bf16.h>
#include <float.h>
#include <stdint.h>

// Problem dims (fixed by setup_inputs)
#define NN   4096
#define FF   512
#define WRDS (NN / 32)
#define K3S  (3 * FF)      // 1536  packed K for feature-dim GEMMs
#define K3N  (3 * NN)      // 12288 packed K for the att@hk GEMM

// ---------------- device scratch (no allocations allowed) ----------------
__device__ float         g_Wh[NN * FF];
__device__ float         g_Wa[NN * FF];
__device__ float         g_hk[NN * FF];
__device__ float         g_src[NN];
__device__ float         g_dst[NN];
__device__ unsigned      g_Abits[NN * WRDS];
__device__ unsigned      g_P[NN * WRDS];
__device__ unsigned      g_Q[NN * WRDS];
__device__ float         g_S[(size_t)NN * NN];          // 64 MB scores
__device__ __nv_bfloat16 g_Xp [(size_t)NN * K3S];       // 12 MB
__device__ __nv_bfloat16 g_WsP[(size_t)FF * K3S];       // 1.5 MB
__device__ __nv_bfloat16 g_WlP[(size_t)FF * K3S];       // 1.5 MB
__device__ __nv_bfloat16 g_hkP[(size_t)NN * K3S];       // 12 MB  (A-pattern)
__device__ __nv_bfloat16 g_WaP[(size_t)NN * K3S];       // 12 MB  (B-pattern)
__device__ __nv_bfloat16 g_hkTP[(size_t)FF * K3N];      // 12 MB  (B-pattern, transposed)
__device__ __nv_bfloat16 g_attP[(size_t)NN * K3N];      // 96 MB  (A-pattern)
__device__ float         g_part[4][(size_t)NN * FF];    // 32 MB split-K partials

// ---------------- helpers ----------------
__device__ __forceinline__ float gelu_tanh(float x) {
    float x3 = x * x * x;
    return 0.5f * x * (1.0f + tanhf(0.7978845608028654f * (x + 0.044715f * x3)));
}
__device__ __forceinline__ uint32_t smem_u32(const void* p) {
    return (uint32_t)__cvta_generic_to_shared(p);
}

// ============================================================
// Tensor-core bf16 NT GEMM: C[M,N] = A[M,K(slice)] * B[N,K(slice)]^T
// CTA 128x128, BK=32, 8 warps (4x2), warp tile 32x64, m16n8k16 mma.
// 2-stage cp.async pipeline. Optional reach-mask epilogue.
// M,N multiples of 128; (kEnd-kBegin) multiple of 32; K row stride.
// ============================================================
template <bool MASKED>
__global__ void __launch_bounds__(256) mma_gemm_nt(
    const __nv_bfloat16* __restrict__ A,
    const __nv_bfloat16* __restrict__ B,
    float* __restrict__ C,
    int M, int N, int K, int kBegin, int kEnd,
    const unsigned* __restrict__ maskbits)
{
    __shared__ __nv_bfloat16 As[2][128][40];   // pad to 40 halfs (80B, 16B-mult)
    __shared__ __nv_bfloat16 Bs[2][128][40];

    const int tid  = threadIdx.x;
    const int bx   = blockIdx.x;    // N tile
    const int by   = blockIdx.y;    // M tile
    const int warp = tid >> 5;
    const int lane = tid & 31;
    const int wm   = (warp >> 1) * 32;   // warp row offset in CTA tile
    const int wn   = (warp & 1) * 64;    // warp col offset

    const __nv_bfloat16* Ag = A + (size_t)(by * 128) * K + kBegin;
    const __nv_bfloat16* Bg = B + (size_t)(bx * 128) * K + kBegin;

    float acc[2][8][4];
#pragma unroll
    for (int mi = 0; mi < 2; mi++)
#pragma unroll
        for (int nj = 0; nj < 8; nj++)
#pragma unroll
            for (int q = 0; q < 4; q++) acc[mi][nj][q] = 0.0f;

    const int nK = (kEnd - kBegin) >> 5;

    auto load_stage = [&](int s, int kc) {
#pragma unroll
        for (int j = 0; j < 2; j++) {
            int idx = tid + j * 256;
            int row = idx >> 2;
            int c4  = idx & 3;
            uint32_t sa = smem_u32(&As[s][row][c4 * 8]);
            const void* ga = Ag + (size_t)row * K + kc * 32 + c4 * 8;
            asm volatile("cp.async.cg.shared.global [%0], [%1], 16;" :: "r"(sa), "l"(ga));
            uint32_t sb = smem_u32(&Bs[s][row][c4 * 8]);
            const void* gb = Bg + (size_t)row * K + kc * 32 + c4 * 8;
            asm volatile("cp.async.cg.shared.global [%0], [%1], 16;" :: "r"(sb), "l"(gb));
        }
    };

    load_stage(0, 0);
    asm volatile("cp.async.commit_group;");

    for (int kc = 0; kc < nK; kc++) {
        const int s = kc & 1;
        if (kc + 1 < nK) load_stage(s ^ 1, kc + 1);
        asm volatile("cp.async.commit_group;");
        asm volatile("cp.async.wait_group 1;");
        __syncthreads();

#pragma unroll
        for (int kk = 0; kk < 32; kk += 16) {
            uint32_t a[2][4];
#pragma unroll
            for (int mi = 0; mi < 2; mi++) {
                int row = wm + mi * 16 + (lane & 7) + ((lane >> 3) & 1) * 8;
                int col = kk + (lane >> 4) * 8;
                uint32_t addr = smem_u32(&As[s][row][col]);
                asm volatile("ldmatrix.sync.aligned.m8n8.x4.shared.b16 {%0,%1,%2,%3},[%4];"
                    : "=r"(a[mi][0]), "=r"(a[mi][1]), "=r"(a[mi][2]), "=r"(a[mi][3])
                    : "r"(addr));
            }
            uint32_t b[8][2];
#pragma unroll
            for (int nj4 = 0; nj4 < 4; nj4++) {
                int row = wn + nj4 * 16 + (lane & 7) + (lane >> 4) * 8;
                int col = kk + ((lane >> 3) & 1) * 8;
                uint32_t addr = smem_u32(&Bs[s][row][col]);
                asm volatile("ldmatrix.sync.aligned.m8n8.x4.shared.b16 {%0,%1,%2,%3},[%4];"
                    : "=r"(b[nj4 * 2][0]), "=r"(b[nj4 * 2][1]),
                      "=r"(b[nj4 * 2 + 1][0]), "=r"(b[nj4 * 2 + 1][1])
                    : "r"(addr));
            }
#pragma unroll
            for (int mi = 0; mi < 2; mi++)
#pragma unroll
                for (int nj = 0; nj < 8; nj++)
                    asm volatile(
                        "mma.sync.aligned.m16n8k16.row.col.f32.bf16.bf16.f32 "
                        "{%0,%1,%2,%3},{%4,%5,%6,%7},{%8,%9},{%0,%1,%2,%3};"
                        : "+f"(acc[mi][nj][0]), "+f"(acc[mi][nj][1]),
                          "+f"(acc[mi][nj][2]), "+f"(acc[mi][nj][3])
                        : "r"(a[mi][0]), "r"(a[mi][1]), "r"(a[mi][2]), "r"(a[mi][3]),
                          "r"(b[nj][0]), "r"(b[nj][1]));
        }
        __syncthreads();
    }

    // epilogue
    const int g = lane >> 2;
    const int c = lane & 3;
#pragma unroll
    for (int mi = 0; mi < 2; mi++) {
#pragma unroll
        for (int nj = 0; nj < 8; nj++) {
            int row0 = by * 128 + wm + mi * 16 + g;
            int row1 = row0 + 8;
            int col  = bx * 128 + wn + nj * 8 + c * 2;
            float v0 = acc[mi][nj][0], v1 = acc[mi][nj][1];
            float v2 = acc[mi][nj][2], v3 = acc[mi][nj][3];
            if (MASKED) {
                unsigned w0 = maskbits[(size_t)row0 * (N / 32) + (col >> 5)];
                unsigned w1 = maskbits[(size_t)row1 * (N / 32) + (col >> 5)];
                if (!((w0 >> (col & 31)) & 1u))       v0 = -FLT_MAX;
                if (!((w0 >> ((col + 1) & 31)) & 1u)) v1 = -FLT_MAX;
                if (!((w1 >> (col & 31)) & 1u))       v2 = -FLT_MAX;
                if (!((w1 >> ((col + 1) & 31)) & 1u)) v3 = -FLT_MAX;
            }
            *reinterpret_cast<float2*>(&C[(size_t)row0 * N + col]) = make_float2(v0, v1);
            *reinterpret_cast<float2*>(&C[(size_t)row1 * N + col]) = make_float2(v2, v3);
        }
    }
}

// ============================================================
// fp32 -> split bf16 packing.
// mode 0 (A-pattern): [hi | hi | lo]; mode 1 (B-pattern): [hi | lo | hi]
// ============================================================
__global__ void pack_split_kernel(const float* __restrict__ in,
                                  __nv_bfloat16* __restrict__ out,
                                  int R, int C, int mode)
{
    int total = R * C;
    for (int idx = blockIdx.x * blockDim.x + threadIdx.x; idx < total;
         idx += gridDim.x * blockDim.x) {
        int r = idx / C, c = idx - r * C;
        float v = in[idx];
        __nv_bfloat16 hi = __float2bfloat16(v);
        __nv_bfloat16 lo = __float2bfloat16(v - __bfloat162float(hi));
        size_t base = (size_t)r * 3 * C;
        out[base + c]         = hi;
        out[base + C + c]     = mode ? lo : hi;
        out[base + 2 * C + c] = mode ? hi : lo;
    }
}

// Transpose + B-pattern pack: in[R x C] fp32 -> out[C x 3R] bf16 (hi|lo|hi)
__global__ void transpose_pack_kernel(const float* __restrict__ in,
                                      __nv_bfloat16* __restrict__ out,
                                      int R, int C)
{
    __shared__ float t[32][33];
    int rb = blockIdx.y * 32;
    int cb = blockIdx.x * 32;
    int tx = threadIdx.x;   // 0..31
    int ty0 = threadIdx.y;  // 0..7
#pragma unroll
    for (int p = 0; p < 4; p++) {
        int ty = ty0 + p * 8;
        t[ty][tx] = in[(size_t)(rb + ty) * C + cb + tx];
    }
    __syncthreads();
#pragma unroll
    for (int p = 0; p < 4; p++) {
        int ty = ty0 + p * 8;               // local col -> output row
        float v = t[tx][ty];                // in[rb+tx][cb+ty]
        __nv_bfloat16 hi = __float2bfloat16(v);
        __nv_bfloat16 lo = __float2bfloat16(v - __bfloat162float(hi));
        size_t base = (size_t)(cb + ty) * 3 * R;
        out[base + rb + tx]         = hi;
        out[base + R + rb + tx]     = lo;
        out[base + 2 * R + rb + tx] = hi;
    }
}

// ============================================================
// adjacency bitset
// ============================================================
__global__ void build_bits_kernel(const float* __restrict__ A, unsigned* __restrict__ bits)
{
    int i = blockIdx.x;
    int w = threadIdx.x;
    const float* row = A + (size_t)i * NN + w * 32;
    unsigned v = 0;
#pragma unroll
    for (int b = 0; b < 32; b++)
        if (row[b] != 0.0f) v |= (1u << b);
    bits[i * WRDS + w] = v;
}

// ============================================================
// src/dst projections
// ============================================================
__global__ void src_dst_kernel(const float* __restrict__ Wh, const float* __restrict__ r,
                               float* __restrict__ src, float* __restrict__ dst)
{
    int warp = (blockIdx.x * blockDim.x + threadIdx.x) >> 5;
    int lane = threadIdx.x & 31;
    if (warp >= NN) return;
    const float* row = Wh + (size_t)warp * FF;
    float a = 0.f, b = 0.f;
    for (int f = lane; f < FF; f += 32) {
        float v = row[f];
        a = fmaf(v, r[f], a);
        b = fmaf(v, r[FF + f], b);
    }
#pragma unroll
    for (int s = 16; s > 0; s >>= 1) {
        a += __shfl_xor_sync(0xffffffffu, a, s);
        b += __shfl_xor_sync(0xffffffffu, b, s);
    }
    if (lane == 0) { src[warp] = a; dst[warp] = b; }
}

// ============================================================
// Short-distance attention (sparse, ~21 nnz/row), fused softmax + SpMM + gelu
// ============================================================
__global__ void __launch_bounds__(256) short_attn_kernel(
    const float* __restrict__ A, const float* __restrict__ Wh,
    const float* __restrict__ src, const float* __restrict__ dst,
    float* __restrict__ hk)
{
    __shared__ int   s_idx[NN];
    __shared__ float s_w[NN];
    __shared__ int   s_scan[256];
    __shared__ float s_red[256];

    const int i   = blockIdx.x;
    const int tid = threadIdx.x;
    const float* Arow = A + (size_t)i * NN;

    const int base = tid * 16;
    unsigned m16 = 0; int c = 0;
#pragma unroll
    for (int q = 0; q < 16; q++)
        if (Arow[base + q] != 0.0f) { m16 |= (1u << q); c++; }
    s_scan[tid] = c;
    __syncthreads();
#pragma unroll
    for (int s = 1; s < 256; s <<= 1) {
        int v = (tid >= s) ? s_scan[tid - s] : 0;
        __syncthreads();
        s_scan[tid] += v;
        __syncthreads();
    }
    int start = s_scan[tid] - c;
    int cnt   = s_scan[255];
    {
        int p = start;
#pragma unroll
        for (int q = 0; q < 16; q++)
            if ((m16 >> q) & 1u) s_idx[p++] = base + q;
    }
    __syncthreads();

    float si = src[i];
    float lmax = -FLT_MAX;
    for (int p = tid; p < cnt; p += 256) {
        float e = si + dst[s_idx[p]];
        e = (e > 0.f) ? e : 0.2f * e;
        s_w[p] = e;
        lmax = fmaxf(lmax, e);
    }
    s_red[tid] = lmax;
    __syncthreads();
#pragma unroll
    for (int s = 128; s > 0; s >>= 1) {
        if (tid < s) s_red[tid] = fmaxf(s_red[tid], s_red[tid + s]);
        __syncthreads();
    }
    float mx = s_red[0];
    __syncthreads();

    float lsum = 0.f;
    for (int p = tid; p < cnt; p += 256) {
        float w = expf(s_w[p] - mx);
        s_w[p] = w;
        lsum += w;
    }
    s_red[tid] = lsum;
    __syncthreads();
#pragma unroll
    for (int s = 128; s > 0; s >>= 1) {
        if (tid < s) s_red[tid] += s_red[tid + s];
        __syncthreads();
    }
    float inv = 1.0f / s_red[0];
    __syncthreads();

    float a0 = 0.f, a1 = 0.f;
    for (int p = 0; p < cnt; p++) {
        float w = s_w[p];
        const float* whr = Wh + (size_t)s_idx[p] * FF;
        a0 = fmaf(w, whr[tid],       a0);
        a1 = fmaf(w, whr[tid + 256], a1);
    }
    hk[(size_t)i * FF + tid]       = gelu_tanh(a0 * inv);
    hk[(size_t)i * FF + tid + 256] = gelu_tanh(a1 * inv);
}

// ============================================================
// One boolean reachability hop (guarded by device-side num_hops)
// ============================================================
__global__ void hop_step_kernel(const unsigned* __restrict__ Abits,
                                const unsigned* __restrict__ src,
                                unsigned* __restrict__ dst,
                                int iter, const int* __restrict__ num_hops)
{
    __shared__ unsigned s_row[WRDS];
    const int i = blockIdx.x;
    const int t = threadIdx.x;
    s_row[t] = Abits[i * WRDS + t];
    __syncthreads();

    if (iter >= (*num_hops) - 1) {
        dst[i * WRDS + t] = src[i * WRDS + t];
        return;
    }
    unsigned acc = 0;
    for (int w = 0; w < WRDS; w++) {
        unsigned bits = s_row[w];
        while (bits) {
            int b = __ffs(bits) - 1;
            bits &= bits - 1;
            acc |= src[(size_t)(w * 32 + b) * WRDS + t];
        }
    }
    dst[i * WRDS + t] = acc;
}

// ============================================================
// Row softmax over 4096-wide rows, fused with A-pattern bf16 packing:
// attP row = [att_hi (4096) | att_hi (4096) | att_lo (4096)]
// ============================================================
__global__ void __launch_bounds__(256) softmax_pack_kernel(
    const float* __restrict__ S, __nv_bfloat16* __restrict__ attP)
{
    __shared__ float s_red[256];
    const int i   = blockIdx.x;
    const int tid = threadIdx.x;
    const float* row = S + (size_t)i * NN;
    __nv_bfloat16* orow = attP + (size_t)i * K3N;

    float vals[16];
    float lmax = -FLT_MAX;
#pragma unroll
    for (int p = 0; p < 16; p++) {
        vals[p] = row[tid + p * 256];
        lmax = fmaxf(lmax, vals[p]);
    }
    s_red[tid] = lmax;
    __syncthreads();
#pragma unroll
    for (int s = 128; s > 0; s >>= 1) {
        if (tid < s) s_red[tid] = fmaxf(s_red[tid], s_red[tid + s]);
        __syncthreads();
    }
    float mx = s_red[0];
    __syncthreads();

    float lsum = 0.f;
#pragma unroll
    for (int p = 0; p < 16; p++) {
        float w = expf(vals[p] - mx);
        vals[p] = w;
        lsum += w;
    }
    s_red[tid] = lsum;
    __syncthreads();
#pragma unroll
    for (int s = 128; s > 0; s >>= 1) {
        if (tid < s) s_red[tid] += s_red[tid + s];
        __syncthreads();
    }
    float inv = 1.0f / s_red[0];
#pragma unroll
    for (int p = 0; p < 16; p++) {
        int j = tid + p * 256;
        float a = vals[p] * inv;
        __nv_bfloat16 hi = __float2bfloat16(a);
        __nv_bfloat16 lo = __float2bfloat16(a - __bfloat162float(hi));
        orow[j]            = hi;
        orow[NN + j]       = hi;
        orow[2 * NN + j]   = lo;
    }
}

// ============================================================
// out = p0 + p1 + p2 + p3   (4096 x 512 fp32)
// ============================================================
__global__ void reduce4_kernel(const float* __restrict__ p0, const float* __restrict__ p1,
                               const float* __restrict__ p2, const float* __restrict__ p3,
                               float* __restrict__ out)
{
    int total = NN * FF / 4;
    for (int idx = blockIdx.x * blockDim.x + threadIdx.x; idx < total;
         idx += gridDim.x * blockDim.x) {
        float4 a = reinterpret_cast<const float4*>(p0)[idx];
        float4 b = reinterpret_cast<const float4*>(p1)[idx];
        float4 c = reinterpret_cast<const float4*>(p2)[idx];
        float4 d = reinterpret_cast<const float4*>(p3)[idx];
        float4 o;
        o.x = a.x + b.x + c.x + d.x;
        o.y = a.y + b.y + c.y + d.y;
        o.z = a.z + b.z + c.z + d.z;
        o.w = a.w + b.w + c.w + d.w;
        reinterpret_cast<float4*>(out)[idx] = o;
    }
}

// ============================================================
// Host launch
// ============================================================
extern "C" void kernel_launch(void* const* d_in, const int* in_sizes, int n_in,
                              void* d_out, int out_size)
{
    const float* X  = (const float*)d_in[0];
    const float* A  = (const float*)d_in[1];
    const float* Ws = (const float*)d_in[2];
    const float* r  = (const float*)d_in[3];
    const float* Wl = (const float*)d_in[4];
    const int*   nh = (const int*)d_in[5];
    float* out = (float*)d_out;

    float *Wh, *Wa, *hk, *src, *dst, *S, *part;
    unsigned *Abits, *P, *Q;
    __nv_bfloat16 *Xp, *WsP, *WlP, *hkP, *WaP, *hkTP, *attP;
    cudaGetSymbolAddress((void**)&Wh,    g_Wh);
    cudaGetSymbolAddress((void**)&Wa,    g_Wa);
    cudaGetSymbolAddress((void**)&hk,    g_hk);
    cudaGetSymbolAddress((void**)&src,   g_src);
    cudaGetSymbolAddress((void**)&dst,   g_dst);
    cudaGetSymbolAddress((void**)&S,     g_S);
    cudaGetSymbolAddress((void**)&Abits, g_Abits);
    cudaGetSymbolAddress((void**)&P,     g_P);
    cudaGetSymbolAddress((void**)&Q,     g_Q);
    cudaGetSymbolAddress((void**)&Xp,    g_Xp);
    cudaGetSymbolAddress((void**)&WsP,   g_WsP);
    cudaGetSymbolAddress((void**)&WlP,   g_WlP);
    cudaGetSymbolAddress((void**)&hkP,   g_hkP);
    cudaGetSymbolAddress((void**)&WaP,   g_WaP);
    cudaGetSymbolAddress((void**)&hkTP,  g_hkTP);
    cudaGetSymbolAddress((void**)&attP,  g_attP);
    cudaGetSymbolAddress((void**)&part,  g_part);

    // pack inputs to split-bf16
    pack_split_kernel<<<1024, 256>>>(X,  Xp,  NN, FF, 0);   // A-pattern
    pack_split_kernel<<<256,  256>>>(Ws, WsP, FF, FF, 1);   // B-pattern
    pack_split_kernel<<<256,  256>>>(Wl, WlP, FF, FF, 1);

    // Wh = X Ws^T ; Wa = X Wl^T   (tensor cores, split-bf16)
    mma_gemm_nt<false><<<dim3(FF / 128, NN / 128), 256>>>(Xp, WsP, Wh, NN, FF, K3S, 0, K3S, nullptr);
    mma_gemm_nt<false><<<dim3(FF / 128, NN / 128), 256>>>(Xp, WlP, Wa, NN, FF, K3S, 0, K3S, nullptr);

    // adjacency bitset + src/dst + short attention -> hk
    build_bits_kernel<<<NN, WRDS>>>(A, Abits);
    src_dst_kernel<<<NN / 8, 256>>>(Wh, r, src, dst);
    short_attn_kernel<<<NN, 256>>>(A, Wh, src, dst, hk);

    // pack hk (A-pattern), Wa (B-pattern), hk^T (B-pattern)
    pack_split_kernel<<<1024, 256>>>(hk, hkP, NN, FF, 0);
    pack_split_kernel<<<1024, 256>>>(Wa, WaP, NN, FF, 1);
    transpose_pack_kernel<<<dim3(FF / 32, NN / 32), dim3(32, 8)>>>(hk, hkTP, NN, FF);

    // multi-hop reachability (boolean), guarded launches; result in Q
    hop_step_kernel<<<NN, WRDS>>>(Abits, Abits, P, 0, nh);
    hop_step_kernel<<<NN, WRDS>>>(Abits, P, Q, 1, nh);
    hop_step_kernel<<<NN, WRDS>>>(Abits, Q, P, 2, nh);
    hop_step_kernel<<<NN, WRDS>>>(Abits, P, Q, 3, nh);
    hop_step_kernel<<<NN, WRDS>>>(Abits, Q, P, 4, nh);
    hop_step_kernel<<<NN, WRDS>>>(Abits, P, Q, 5, nh);

    // scores = hk Wa^T with reach mask -> S (fp32)
    mma_gemm_nt<true><<<dim3(NN / 128, NN / 128), 256>>>(hkP, WaP, S, NN, NN, K3S, 0, K3S, Q);

    // softmax + pack att to split-bf16 (A-pattern)
    softmax_pack_kernel<<<NN, 256>>>(S, attP);

    // ok = att2 hk  (split-K = 4 over packed K3N)
    for (int sK = 0; sK < 4; sK++) {
        mma_gemm_nt<false><<<dim3(FF / 128, NN / 128), 256>>>(
            attP, hkTP, part + (size_t)sK * NN * FF,
            NN, FF, K3N, sK * (K3N / 4), (sK + 1) * (K3N / 4), nullptr);
    }
    reduce4_kernel<<<1024, 256>>>(part, part + (size_t)NN * FF,
                                  part + (size_t)2 * NN * FF, part + (size_t)3 * NN * FF, out);
}

// round 4
// speedup vs baseline: 2.4065x; 1.1771x over previous
#include <cuda_runtime.h>
#include <cuda_bf16.h>
#include <float.h>
#include <stdint.h>

// Problem dims (fixed by setup_inputs)
#define NN   4096
#define FF   512
#define WRDS (NN / 32)
#define K3S  (3 * FF)      // 1536  packed K for feature-dim GEMMs
#define K3N  (3 * NN)      // 12288 packed K for the att@hk GEMM
#define NSPLIT 8

// ---------------- device scratch (no allocations allowed) ----------------
__device__ float         g_Wh[NN * FF];
__device__ float         g_Wa[NN * FF];
__device__ float         g_hk[NN * FF];
__device__ float         g_src[NN];
__device__ float         g_dst[NN];
__device__ unsigned      g_Abits[NN * WRDS];
__device__ unsigned      g_P[NN * WRDS];
__device__ unsigned      g_Q[NN * WRDS];
__device__ float         g_S[(size_t)NN * NN];          // 64 MB scores
__device__ __nv_bfloat16 g_Xp [(size_t)NN * K3S];
__device__ __nv_bfloat16 g_WsP[(size_t)FF * K3S];
__device__ __nv_bfloat16 g_WlP[(size_t)FF * K3S];
__device__ __nv_bfloat16 g_hkP[(size_t)NN * K3S];
__device__ __nv_bfloat16 g_WaP[(size_t)NN * K3S];
__device__ __nv_bfloat16 g_hkTP[(size_t)FF * K3N];
__device__ __nv_bfloat16 g_attP[(size_t)NN * K3N];      // 96 MB
__device__ float         g_part[NSPLIT][(size_t)NN * FF]; // 64 MB split-K partials

// ---------------- helpers ----------------
__device__ __forceinline__ float gelu_tanh(float x) {
    float x3 = x * x * x;
    return 0.5f * x * (1.0f + tanhf(0.7978845608028654f * (x + 0.044715f * x3)));
}
__device__ __forceinline__ uint32_t smem_u32(const void* p) {
    return (uint32_t)__cvta_generic_to_shared(p);
}

// ============================================================
// Tensor-core bf16 NT GEMM: C[M,N] = A[M,Kslice] * B[N,Kslice]^T
// CTA 128x128, 4 warps (2x2), warp tile 64x64, BK=32, 3-stage cp.async.
// DUAL:   blockIdx.z selects (B,C) vs (B2,C2)         [two GEMMs, one launch]
// SPLITK: blockIdx.z selects K slice; C += z*M*N      [split-K partials]
// MASKED: reach-mask epilogue (masked -> -FLT_MAX)
// ============================================================
#define BK     32
#define SSTR   40            // padded halfs per row (80B, 16B multiple)
#define NSTG   3
#define STG_A_BYTES (128 * SSTR * 2)

template <bool MASKED, bool SPLITK, bool DUAL>
__global__ void __launch_bounds__(128) mma_gemm_nt(
    const __nv_bfloat16* __restrict__ A,
    const __nv_bfloat16* __restrict__ B,
    const __nv_bfloat16* __restrict__ B2,
    float* __restrict__ C,
    float* __restrict__ C2,
    int M, int N, int K, int kSlice,
    const unsigned* __restrict__ maskbits)
{
    extern __shared__ __align__(16) unsigned char smem_raw[];
    __nv_bfloat16* AsBase = (__nv_bfloat16*)smem_raw;                 // [NSTG][128][SSTR]
    __nv_bfloat16* BsBase = AsBase + NSTG * 128 * SSTR;

    const int tid  = threadIdx.x;
    const int bx   = blockIdx.x;    // N tile
    const int by   = blockIdx.y;    // M tile
    const int bz   = blockIdx.z;
    const int warp = tid >> 5;
    const int lane = tid & 31;
    const int wm   = (warp >> 1) * 64;
    const int wn   = (warp & 1) * 64;

    const __nv_bfloat16* Bsel = (DUAL && bz) ? B2 : B;
    float* Csel = (DUAL && bz) ? C2 : C;
    int kBegin = 0, kLen = K;
    if (SPLITK) { kBegin = bz * kSlice; kLen = kSlice; Csel = C + (size_t)bz * M * N; }

    const __nv_bfloat16* Ag = A    + (size_t)(by * 128) * K + kBegin;
    const __nv_bfloat16* Bg = Bsel + (size_t)(bx * 128) * K + kBegin;

    float acc[4][8][4];
#pragma unroll
    for (int mi = 0; mi < 4; mi++)
#pragma unroll
        for (int nj = 0; nj < 8; nj++)
#pragma unroll
            for (int q = 0; q < 4; q++) acc[mi][nj][q] = 0.0f;

    const int nK = kLen >> 5;   // BK=32 chunks

    auto load_stage = [&](int s, int kc) {
        __nv_bfloat16* As = AsBase + s * 128 * SSTR;
        __nv_bfloat16* Bs = BsBase + s * 128 * SSTR;
#pragma unroll
        for (int j = 0; j < 4; j++) {
            int idx = tid + j * 128;        // 512 chunks of 16B
            int row = idx >> 2;
            int c4  = idx & 3;
            uint32_t sa = smem_u32(&As[row * SSTR + c4 * 8]);
            const void* ga = Ag + (size_t)row * K + kc * 32 + c4 * 8;
            asm volatile("cp.async.cg.shared.global [%0], [%1], 16;" :: "r"(sa), "l"(ga));
            uint32_t sb = smem_u32(&Bs[row * SSTR + c4 * 8]);
            const void* gb = Bg + (size_t)row * K + kc * 32 + c4 * 8;
            asm volatile("cp.async.cg.shared.global [%0], [%1], 16;" :: "r"(sb), "l"(gb));
        }
    };

    load_stage(0, 0);
    asm volatile("cp.async.commit_group;");
    load_stage(1, 1);
    asm volatile("cp.async.commit_group;");

    for (int kc = 0; kc < nK; kc++) {
        const int s = kc % NSTG;
        asm volatile("cp.async.wait_group 1;");
        __syncthreads();

        const __nv_bfloat16* As = AsBase + s * 128 * SSTR;
        const __nv_bfloat16* Bs = BsBase + s * 128 * SSTR;

#pragma unroll
        for (int kk = 0; kk < BK; kk += 16) {
            uint32_t a[4][4];
#pragma unroll
            for (int mi = 0; mi < 4; mi++) {
                int row = wm + mi * 16 + (lane & 7) + ((lane >> 3) & 1) * 8;
                int col = kk + (lane >> 4) * 8;
                uint32_t addr = smem_u32(&As[row * SSTR + col]);
                asm volatile("ldmatrix.sync.aligned.m8n8.x4.shared.b16 {%0,%1,%2,%3},[%4];"
                    : "=r"(a[mi][0]), "=r"(a[mi][1]), "=r"(a[mi][2]), "=r"(a[mi][3])
                    : "r"(addr));
            }
            uint32_t b[8][2];
#pragma unroll
            for (int nj4 = 0; nj4 < 4; nj4++) {
                int row = wn + nj4 * 16 + (lane & 7) + (lane >> 4) * 8;
                int col = kk + ((lane >> 3) & 1) * 8;
                uint32_t addr = smem_u32(&Bs[row * SSTR + col]);
                asm volatile("ldmatrix.sync.aligned.m8n8.x4.shared.b16 {%0,%1,%2,%3},[%4];"
                    : "=r"(b[nj4 * 2][0]), "=r"(b[nj4 * 2][1]),
                      "=r"(b[nj4 * 2 + 1][0]), "=r"(b[nj4 * 2 + 1][1])
                    : "r"(addr));
            }
#pragma unroll
            for (int mi = 0; mi < 4; mi++)
#pragma unroll
                for (int nj = 0; nj < 8; nj++)
                    asm volatile(
                        "mma.sync.aligned.m16n8k16.row.col.f32.bf16.bf16.f32 "
                        "{%0,%1,%2,%3},{%4,%5,%6,%7},{%8,%9},{%0,%1,%2,%3};"
                        : "+f"(acc[mi][nj][0]), "+f"(acc[mi][nj][1]),
                          "+f"(acc[mi][nj][2]), "+f"(acc[mi][nj][3])
                        : "r"(a[mi][0]), "r"(a[mi][1]), "r"(a[mi][2]), "r"(a[mi][3]),
                          "r"(b[nj][0]), "r"(b[nj][1]));
        }
        __syncthreads();
        if (kc + 2 < nK) load_stage((kc + 2) % NSTG, kc + 2);
        asm volatile("cp.async.commit_group;");
    }
    asm volatile("cp.async.wait_group 0;");

    // epilogue
    const int g = lane >> 2;
    const int c = lane & 3;
#pragma unroll
    for (int mi = 0; mi < 4; mi++) {
#pragma unroll
        for (int nj = 0; nj < 8; nj++) {
            int row0 = by * 128 + wm + mi * 16 + g;
            int row1 = row0 + 8;
            int col  = bx * 128 + wn + nj * 8 + c * 2;
            float v0 = acc[mi][nj][0], v1 = acc[mi][nj][1];
            float v2 = acc[mi][nj][2], v3 = acc[mi][nj][3];
            if (MASKED) {
                unsigned w0 = maskbits[(size_t)row0 * (N / 32) + (col >> 5)];
                unsigned w1 = maskbits[(size_t)row1 * (N / 32) + (col >> 5)];
                if (!((w0 >> (col & 31)) & 1u))       v0 = -FLT_MAX;
                if (!((w0 >> ((col + 1) & 31)) & 1u)) v1 = -FLT_MAX;
                if (!((w1 >> (col & 31)) & 1u))       v2 = -FLT_MAX;
                if (!((w1 >> ((col + 1) & 31)) & 1u)) v3 = -FLT_MAX;
            }
            *reinterpret_cast<float2*>(&Csel[(size_t)row0 * N + col]) = make_float2(v0, v1);
            *reinterpret_cast<float2*>(&Csel[(size_t)row1 * N + col]) = make_float2(v2, v3);
        }
    }
}

// ============================================================
// fp32 -> split bf16 packing. mode 0: [hi|hi|lo], mode 1: [hi|lo|hi]
// ============================================================
__global__ void pack_split_kernel(const float* __restrict__ in,
                                  __nv_bfloat16* __restrict__ out,
                                  int R, int C, int mode)
{
    int total = R * C;
    for (int idx = blockIdx.x * blockDim.x + threadIdx.x; idx < total;
         idx += gridDim.x * blockDim.x) {
        int r = idx / C, c = idx - r * C;
        float v = in[idx];
        __nv_bfloat16 hi = __float2bfloat16(v);
        __nv_bfloat16 lo = __float2bfloat16(v - __bfloat162float(hi));
        size_t base = (size_t)r * 3 * C;
        out[base + c]         = hi;
        out[base + C + c]     = mode ? lo : hi;
        out[base + 2 * C + c] = mode ? hi : lo;
    }
}

// Transpose + B-pattern pack: in[R x C] fp32 -> out[C x 3R] bf16 (hi|lo|hi)
__global__ void transpose_pack_kernel(const float* __restrict__ in,
                                      __nv_bfloat16* __restrict__ out,
                                      int R, int C)
{
    __shared__ float t[32][33];
    int rb = blockIdx.y * 32;
    int cb = blockIdx.x * 32;
    int tx = threadIdx.x;
    int ty0 = threadIdx.y;
#pragma unroll
    for (int p = 0; p < 4; p++) {
        int ty = ty0 + p * 8;
        t[ty][tx] = in[(size_t)(rb + ty) * C + cb + tx];
    }
    __syncthreads();
#pragma unroll
    for (int p = 0; p < 4; p++) {
        int ty = ty0 + p * 8;
        float v = t[tx][ty];
        __nv_bfloat16 hi = __float2bfloat16(v);
        __nv_bfloat16 lo = __float2bfloat16(v - __bfloat162float(hi));
        size_t base = (size_t)(cb + ty) * 3 * R;
        out[base + rb + tx]         = hi;
        out[base + R + rb + tx]     = lo;
        out[base + 2 * R + rb + tx] = hi;
    }
}

// ============================================================
__global__ void build_bits_kernel(const float* __restrict__ A, unsigned* __restrict__ bits)
{
    int i = blockIdx.x;
    int w = threadIdx.x;
    const float* row = A + (size_t)i * NN + w * 32;
    unsigned v = 0;
#pragma unroll
    for (int b = 0; b < 32; b++)
        if (row[b] != 0.0f) v |= (1u << b);
    bits[i * WRDS + w] = v;
}

// ============================================================
__global__ void src_dst_kernel(const float* __restrict__ Wh, const float* __restrict__ r,
                               float* __restrict__ src, float* __restrict__ dst)
{
    int warp = (blockIdx.x * blockDim.x + threadIdx.x) >> 5;
    int lane = threadIdx.x & 31;
    if (warp >= NN) return;
    const float* row = Wh + (size_t)warp * FF;
    float a = 0.f, b = 0.f;
    for (int f = lane; f < FF; f += 32) {
        float v = row[f];
        a = fmaf(v, r[f], a);
        b = fmaf(v, r[FF + f], b);
    }
#pragma unroll
    for (int s = 16; s > 0; s >>= 1) {
        a += __shfl_xor_sync(0xffffffffu, a, s);
        b += __shfl_xor_sync(0xffffffffu, b, s);
    }
    if (lane == 0) { src[warp] = a; dst[warp] = b; }
}

// ============================================================
// Short-distance attention (sparse), fused softmax + SpMM + gelu
// ============================================================
__global__ void __launch_bounds__(256) short_attn_kernel(
    const float* __restrict__ A, const float* __restrict__ Wh,
    const float* __restrict__ src, const float* __restrict__ dst,
    float* __restrict__ hk)
{
    __shared__ int   s_idx[NN];
    __shared__ float s_w[NN];
    __shared__ int   s_scan[256];
    __shared__ float s_red[256];

    const int i   = blockIdx.x;
    const int tid = threadIdx.x;
    const float* Arow = A + (size_t)i * NN;

    const int base = tid * 16;
    unsigned m16 = 0; int c = 0;
#pragma unroll
    for (int q = 0; q < 16; q++)
        if (Arow[base + q] != 0.0f) { m16 |= (1u << q); c++; }
    s_scan[tid] = c;
    __syncthreads();
#pragma unroll
    for (int s = 1; s < 256; s <<= 1) {
        int v = (tid >= s) ? s_scan[tid - s] : 0;
        __syncthreads();
        s_scan[tid] += v;
        __syncthreads();
    }
    int start = s_scan[tid] - c;
    int cnt   = s_scan[255];
    {
        int p = start;
#pragma unroll
        for (int q = 0; q < 16; q++)
            if ((m16 >> q) & 1u) s_idx[p++] = base + q;
    }
    __syncthreads();

    float si = src[i];
    float lmax = -FLT_MAX;
    for (int p = tid; p < cnt; p += 256) {
        float e = si + dst[s_idx[p]];
        e = (e > 0.f) ? e : 0.2f * e;
        s_w[p] = e;
        lmax = fmaxf(lmax, e);
    }
    s_red[tid] = lmax;
    __syncthreads();
#pragma unroll
    for (int s = 128; s > 0; s >>= 1) {
        if (tid < s) s_red[tid] = fmaxf(s_red[tid], s_red[tid + s]);
        __syncthreads();
    }
    float mx = s_red[0];
    __syncthreads();

    float lsum = 0.f;
    for (int p = tid; p < cnt; p += 256) {
        float w = expf(s_w[p] - mx);
        s_w[p] = w;
        lsum += w;
    }
    s_red[tid] = lsum;
    __syncthreads();
#pragma unroll
    for (int s = 128; s > 0; s >>= 1) {
        if (tid < s) s_red[tid] += s_red[tid + s];
        __syncthreads();
    }
    float inv = 1.0f / s_red[0];
    __syncthreads();

    float a0 = 0.f, a1 = 0.f;
    for (int p = 0; p < cnt; p++) {
        float w = s_w[p];
        const float* whr = Wh + (size_t)s_idx[p] * FF;
        a0 = fmaf(w, whr[tid],       a0);
        a1 = fmaf(w, whr[tid + 256], a1);
    }
    hk[(size_t)i * FF + tid]       = gelu_tanh(a0 * inv);
    hk[(size_t)i * FF + tid + 256] = gelu_tanh(a1 * inv);
}

// ============================================================
__global__ void hop_step_kernel(const unsigned* __restrict__ Abits,
                                const unsigned* __restrict__ src,
                                unsigned* __restrict__ dst,
                                int iter, const int* __restrict__ num_hops)
{
    __shared__ unsigned s_row[WRDS];
    const int i = blockIdx.x;
    const int t = threadIdx.x;
    s_row[t] = Abits[i * WRDS + t];
    __syncthreads();

    if (iter >= (*num_hops) - 1) {
        dst[i * WRDS + t] = src[i * WRDS + t];
        return;
    }
    unsigned acc = 0;
    for (int w = 0; w < WRDS; w++) {
        unsigned bits = s_row[w];
        while (bits) {
            int b = __ffs(bits) - 1;
            bits &= bits - 1;
            acc |= src[(size_t)(w * 32 + b) * WRDS + t];
        }
    }
    dst[i * WRDS + t] = acc;
}

// ============================================================
// Row softmax (4096-wide) fused with A-pattern bf16 packing
// ============================================================
__global__ void __launch_bounds__(256) softmax_pack_kernel(
    const float* __restrict__ S, __nv_bfloat16* __restrict__ attP)
{
    __shared__ float s_red[256];
    const int i   = blockIdx.x;
    const int tid = threadIdx.x;
    const float* row = S + (size_t)i * NN;
    __nv_bfloat16* orow = attP + (size_t)i * K3N;

    float vals[16];
    float lmax = -FLT_MAX;
#pragma unroll
    for (int p = 0; p < 16; p++) {
        vals[p] = row[tid + p * 256];
        lmax = fmaxf(lmax, vals[p]);
    }
    s_red[tid] = lmax;
    __syncthreads();
#pragma unroll
    for (int s = 128; s > 0; s >>= 1) {
        if (tid < s) s_red[tid] = fmaxf(s_red[tid], s_red[tid + s]);
        __syncthreads();
    }
    float mx = s_red[0];
    __syncthreads();

    float lsum = 0.f;
#pragma unroll
    for (int p = 0; p < 16; p++) {
        float w = expf(vals[p] - mx);
        vals[p] = w;
        lsum += w;
    }
    s_red[tid] = lsum;
    __syncthreads();
#pragma unroll
    for (int s = 128; s > 0; s >>= 1) {
        if (tid < s) s_red[tid] += s_red[tid + s];
        __syncthreads();
    }
    float inv = 1.0f / s_red[0];
#pragma unroll
    for (int p = 0; p < 16; p++) {
        int j = tid + p * 256;
        float a = vals[p] * inv;
        __nv_bfloat16 hi = __float2bfloat16(a);
        __nv_bfloat16 lo = __float2bfloat16(a - __bfloat162float(hi));
        orow[j]            = hi;
        orow[NN + j]       = hi;
        orow[2 * NN + j]   = lo;
    }
}

// ============================================================
// out = sum of 8 partials  (4096 x 512 fp32)
// ============================================================
__global__ void reduce8_kernel(const float* __restrict__ part, float* __restrict__ out)
{
    int total = NN * FF / 4;
    const size_t stride = (size_t)NN * FF / 4;
    for (int idx = blockIdx.x * blockDim.x + threadIdx.x; idx < total;
         idx += gridDim.x * blockDim.x) {
        float4 o = make_float4(0.f, 0.f, 0.f, 0.f);
#pragma unroll
        for (int s = 0; s < NSPLIT; s++) {
            float4 a = reinterpret_cast<const float4*>(part)[idx + s * stride];
            o.x += a.x; o.y += a.y; o.z += a.z; o.w += a.w;
        }
        reinterpret_cast<float4*>(out)[idx] = o;
    }
}

// ============================================================
// Host launch
// ============================================================
extern "C" void kernel_launch(void* const* d_in, const int* in_sizes, int n_in,
                              void* d_out, int out_size)
{
    const float* X  = (const float*)d_in[0];
    const float* A  = (const float*)d_in[1];
    const float* Ws = (const float*)d_in[2];
    const float* r  = (const float*)d_in[3];
    const float* Wl = (const float*)d_in[4];
    const int*   nh = (const int*)d_in[5];
    float* out = (float*)d_out;

    float *Wh, *Wa, *hk, *src, *dst, *S, *part;
    unsigned *Abits, *P, *Q;
    __nv_bfloat16 *Xp, *WsP, *WlP, *hkP, *WaP, *hkTP, *attP;
    cudaGetSymbolAddress((void**)&Wh,    g_Wh);
    cudaGetSymbolAddress((void**)&Wa,    g_Wa);
    cudaGetSymbolAddress((void**)&hk,    g_hk);
    cudaGetSymbolAddress((void**)&src,   g_src);
    cudaGetSymbolAddress((void**)&dst,   g_dst);
    cudaGetSymbolAddress((void**)&S,     g_S);
    cudaGetSymbolAddress((void**)&Abits, g_Abits);
    cudaGetSymbolAddress((void**)&P,     g_P);
    cudaGetSymbolAddress((void**)&Q,     g_Q);
    cudaGetSymbolAddress((void**)&Xp,    g_Xp);
    cudaGetSymbolAddress((void**)&WsP,   g_WsP);
    cudaGetSymbolAddress((void**)&WlP,   g_WlP);
    cudaGetSymbolAddress((void**)&hkP,   g_hkP);
    cudaGetSymbolAddress((void**)&WaP,   g_WaP);
    cudaGetSymbolAddress((void**)&hkTP,  g_hkTP);
    cudaGetSymbolAddress((void**)&attP,  g_attP);
    cudaGetSymbolAddress((void**)&part,  g_part);

    const int smemBytes = NSTG * 2 * 128 * SSTR * 2;   // 61440
    cudaFuncSetAttribute(mma_gemm_nt<false, false, true>,
                         cudaFuncAttributeMaxDynamicSharedMemorySize, smemBytes);
    cudaFuncSetAttribute(mma_gemm_nt<true, false, false>,
                         cudaFuncAttributeMaxDynamicSharedMemorySize, smemBytes);
    cudaFuncSetAttribute(mma_gemm_nt<false, true, false>,
                         cudaFuncAttributeMaxDynamicSharedMemorySize, smemBytes);

    // pack inputs to split-bf16
    pack_split_kernel<<<1024, 256>>>(X,  Xp,  NN, FF, 0);
    pack_split_kernel<<<256,  256>>>(Ws, WsP, FF, FF, 1);
    pack_split_kernel<<<256,  256>>>(Wl, WlP, FF, FF, 1);

    // Wh = X Ws^T and Wa = X Wl^T in ONE dual launch
    mma_gemm_nt<false, false, true><<<dim3(FF / 128, NN / 128, 2), 128, smemBytes>>>(
        Xp, WsP, WlP, Wh, Wa, NN, FF, K3S, K3S, nullptr);

    // adjacency bitset + src/dst + short attention -> hk
    build_bits_kernel<<<NN, WRDS>>>(A, Abits);
    src_dst_kernel<<<NN / 8, 256>>>(Wh, r, src, dst);
    short_attn_kernel<<<NN, 256>>>(A, Wh, src, dst, hk);

    // pack hk (A-pattern), Wa (B-pattern), hk^T (B-pattern)
    pack_split_kernel<<<1024, 256>>>(hk, hkP, NN, FF, 0);
    pack_split_kernel<<<1024, 256>>>(Wa, WaP, NN, FF, 1);
    transpose_pack_kernel<<<dim3(FF / 32, NN / 32), dim3(32, 8)>>>(hk, hkTP, NN, FF);

    // multi-hop reachability (boolean), guarded launches; result in Q
    hop_step_kernel<<<NN, WRDS>>>(Abits, Abits, P, 0, nh);
    hop_step_kernel<<<NN, WRDS>>>(Abits, P, Q, 1, nh);
    hop_step_kernel<<<NN, WRDS>>>(Abits, Q, P, 2, nh);
    hop_step_kernel<<<NN, WRDS>>>(Abits, P, Q, 3, nh);
    hop_step_kernel<<<NN, WRDS>>>(Abits, Q, P, 4, nh);
    hop_step_kernel<<<NN, WRDS>>>(Abits, P, Q, 5, nh);

    // scores = hk Wa^T with reach mask -> S (fp32)
    mma_gemm_nt<true, false, false><<<dim3(NN / 128, NN / 128), 128, smemBytes>>>(
        hkP, WaP, nullptr, S, nullptr, NN, NN, K3S, K3S, Q);

    // softmax + pack att to split-bf16 (A-pattern)
    softmax_pack_kernel<<<NN, 256>>>(S, attP);

    // ok = att2 hk  (split-K = 8, single launch) + reduce
    mma_gemm_nt<false, true, false><<<dim3(FF / 128, NN / 128, NSPLIT), 128, smemBytes>>>(
        attP, hkTP, nullptr, part, nullptr, NN, FF, K3N, K3N / NSPLIT, nullptr);
    reduce8_kernel<<<1024, 256>>>(part, out);
}

// round 7
// speedup vs baseline: 2.5095x; 1.0428x over previous
#include <cuda_runtime.h>
#include <cuda_bf16.h>
#include <float.h>
#include <stdint.h>

// Problem dims (fixed by setup_inputs)
#define NN   4096
#define FF   512
#define WRDS (NN / 32)
#define K3S  (3 * FF)      // 1536  packed K for feature-dim GEMMs
#define K3N  (3 * NN)      // 12288 packed K for the att@hk GEMM
#define NSPLIT 8

// ---------------- device scratch (no allocations allowed) ----------------
__device__ float         g_Wh[NN * FF];
__device__ float         g_Wa[NN * FF];
__device__ float         g_hk[NN * FF];
__device__ float         g_src[NN];
__device__ float         g_dst[NN];
__device__ unsigned      g_Abits[NN * WRDS];
__device__ unsigned      g_P[NN * WRDS];
__device__ unsigned      g_Q[NN * WRDS];
__device__ float         g_S[(size_t)NN * NN];          // 64 MB scores
__device__ __nv_bfloat16 g_Xp [(size_t)NN * K3S];
__device__ __nv_bfloat16 g_WsP[(size_t)FF * K3S];
__device__ __nv_bfloat16 g_WlP[(size_t)FF * K3S];
__device__ __nv_bfloat16 g_hkP[(size_t)NN * K3S];
__device__ __nv_bfloat16 g_WaP[(size_t)NN * K3S];
__device__ __nv_bfloat16 g_hkTP[(size_t)FF * K3N];
__device__ __nv_bfloat16 g_attP[(size_t)NN * K3N];      // 96 MB
__device__ float         g_part[NSPLIT][(size_t)NN * FF]; // 64 MB split-K partials

// ---------------- helpers ----------------
__device__ __forceinline__ float gelu_tanh(float x) {
    float x3 = x * x * x;
    return 0.5f * x * (1.0f + tanhf(0.7978845608028654f * (x + 0.044715f * x3)));
}
__device__ __forceinline__ uint32_t smem_u32(const void* p) {
    return (uint32_t)__cvta_generic_to_shared(p);
}

// ============================================================
// Tensor-core bf16 NT GEMM: C[M,N] = A[M,Kslice] * B[N,Kslice]^T
// CTA 128x128, 4 warps (2x2), warp tile 64x64, BK=64, 2-stage cp.async.
// DUAL:   blockIdx.z selects (B,C) vs (B2,C2)
// SPLITK: blockIdx.z selects K slice; C += z*M*N
// MASKED: reach-mask epilogue (masked -> -FLT_MAX)
// ============================================================
#define BK     64
#define SSTR   72            // padded halfs per row (144B, 16B multiple)
#define NSTG   2

template <bool MASKED, bool SPLITK, bool DUAL>
__global__ void __launch_bounds__(128) mma_gemm_nt(
    const __nv_bfloat16* __restrict__ A,
    const __nv_bfloat16* __restrict__ B,
    const __nv_bfloat16* __restrict__ B2,
    float* __restrict__ C,
    float* __restrict__ C2,
    int M, int N, int K, int kSlice,
    const unsigned* __restrict__ maskbits)
{
    extern __shared__ __align__(16) unsigned char smem_raw[];
    __nv_bfloat16* AsBase = (__nv_bfloat16*)smem_raw;                 // [NSTG][128][SSTR]
    __nv_bfloat16* BsBase = AsBase + NSTG * 128 * SSTR;

    const int tid  = threadIdx.x;
    const int bx   = blockIdx.x;    // N tile
    const int by   = blockIdx.y;    // M tile
    const int bz   = blockIdx.z;
    const int warp = tid >> 5;
    const int lane = tid & 31;
    const int wm   = (warp >> 1) * 64;
    const int wn   = (warp & 1) * 64;

    const __nv_bfloat16* Bsel = (DUAL && bz) ? B2 : B;
    float* Csel = (DUAL && bz) ? C2 : C;
    int kBegin = 0, kLen = K;
    if (SPLITK) { kBegin = bz * kSlice; kLen = kSlice; Csel = C + (size_t)bz * M * N; }

    const __nv_bfloat16* Ag = A    + (size_t)(by * 128) * K + kBegin;
    const __nv_bfloat16* Bg = Bsel + (size_t)(bx * 128) * K + kBegin;

    float acc[4][8][4];
#pragma unroll
    for (int mi = 0; mi < 4; mi++)
#pragma unroll
        for (int nj = 0; nj < 8; nj++)
#pragma unroll
            for (int q = 0; q < 4; q++) acc[mi][nj][q] = 0.0f;

    const int nK = kLen / BK;   // BK=64 chunks

    auto load_stage = [&](int s, int kc) {
        __nv_bfloat16* As = AsBase + s * 128 * SSTR;
        __nv_bfloat16* Bs = BsBase + s * 128 * SSTR;
#pragma unroll
        for (int j = 0; j < 8; j++) {
            int idx = tid + j * 128;        // 1024 chunks of 16B per matrix
            int row = idx >> 3;             // 0..127
            int c   = idx & 7;              // 16B chunk within 128B row
            uint32_t sa = smem_u32(&As[row * SSTR + c * 8]);
            const void* ga = Ag + (size_t)row * K + kc * BK + c * 8;
            asm volatile("cp.async.cg.shared.global [%0], [%1], 16;" :: "r"(sa), "l"(ga));
            uint32_t sb = smem_u32(&Bs[row * SSTR + c * 8]);
            const void* gb = Bg + (size_t)row * K + kc * BK + c * 8;
            asm volatile("cp.async.cg.shared.global [%0], [%1], 16;" :: "r"(sb), "l"(gb));
        }
    };

    load_stage(0, 0);
    asm volatile("cp.async.commit_group;");

    for (int kc = 0; kc < nK; kc++) {
        const int s = kc & 1;
        if (kc + 1 < nK) {
            load_stage(s ^ 1, kc + 1);
            asm volatile("cp.async.commit_group;");
            asm volatile("cp.async.wait_group 1;");
        } else {
            asm volatile("cp.async.wait_group 0;");
        }
        __syncthreads();

        const __nv_bfloat16* As = AsBase + s * 128 * SSTR;
        const __nv_bfloat16* Bs = BsBase + s * 128 * SSTR;

#pragma unroll
        for (int kk = 0; kk < BK; kk += 16) {
            uint32_t a[4][4];
#pragma unroll
            for (int mi = 0; mi < 4; mi++) {
                int row = wm + mi * 16 + (lane & 7) + ((lane >> 3) & 1) * 8;
                int col = kk + (lane >> 4) * 8;
                uint32_t addr = smem_u32(&As[row * SSTR + col]);
                asm volatile("ldmatrix.sync.aligned.m8n8.x4.shared.b16 {%0,%1,%2,%3},[%4];"
                    : "=r"(a[mi][0]), "=r"(a[mi][1]), "=r"(a[mi][2]), "=r"(a[mi][3])
                    : "r"(addr));
            }
            uint32_t b[8][2];
#pragma unroll
            for (int nj4 = 0; nj4 < 4; nj4++) {
                int row = wn + nj4 * 16 + (lane & 7) + (lane >> 4) * 8;
                int col = kk + ((lane >> 3) & 1) * 8;
                uint32_t addr = smem_u32(&Bs[row * SSTR + col]);
                asm volatile("ldmatrix.sync.aligned.m8n8.x4.shared.b16 {%0,%1,%2,%3},[%4];"
                    : "=r"(b[nj4 * 2][0]), "=r"(b[nj4 * 2][1]),
                      "=r"(b[nj4 * 2 + 1][0]), "=r"(b[nj4 * 2 + 1][1])
                    : "r"(addr));
            }
#pragma unroll
            for (int mi = 0; mi < 4; mi++)
#pragma unroll
                for (int nj = 0; nj < 8; nj++)
                    asm volatile(
                        "mma.sync.aligned.m16n8k16.row.col.f32.bf16.bf16.f32 "
                        "{%0,%1,%2,%3},{%4,%5,%6,%7},{%8,%9},{%0,%1,%2,%3};"
                        : "+f"(acc[mi][nj][0]), "+f"(acc[mi][nj][1]),
                          "+f"(acc[mi][nj][2]), "+f"(acc[mi][nj][3])
                        : "r"(a[mi][0]), "r"(a[mi][1]), "r"(a[mi][2]), "r"(a[mi][3]),
                          "r"(b[nj][0]), "r"(b[nj][1]));
        }
        __syncthreads();
    }

    // epilogue
    const int g = lane >> 2;
    const int c = lane & 3;
#pragma unroll
    for (int mi = 0; mi < 4; mi++) {
#pragma unroll
        for (int nj = 0; nj < 8; nj++) {
            int row0 = by * 128 + wm + mi * 16 + g;
            int row1 = row0 + 8;
            int col  = bx * 128 + wn + nj * 8 + c * 2;
            float v0 = acc[mi][nj][0], v1 = acc[mi][nj][1];
            float v2 = acc[mi][nj][2], v3 = acc[mi][nj][3];
            if (MASKED) {
                unsigned w0 = maskbits[(size_t)row0 * (N / 32) + (col >> 5)];
                unsigned w1 = maskbits[(size_t)row1 * (N / 32) + (col >> 5)];
                if (!((w0 >> (col & 31)) & 1u))       v0 = -FLT_MAX;
                if (!((w0 >> ((col + 1) & 31)) & 1u)) v1 = -FLT_MAX;
                if (!((w1 >> (col & 31)) & 1u))       v2 = -FLT_MAX;
                if (!((w1 >> ((col + 1) & 31)) & 1u)) v3 = -FLT_MAX;
            }
            *reinterpret_cast<float2*>(&Csel[(size_t)row0 * N + col]) = make_float2(v0, v1);
            *reinterpret_cast<float2*>(&Csel[(size_t)row1 * N + col]) = make_float2(v2, v3);
        }
    }
}

// ============================================================
// fp32 -> split bf16 packing. mode 0: [hi|hi|lo], mode 1: [hi|lo|hi]
// ============================================================
__global__ void pack_split_kernel(const float* __restrict__ in,
                                  __nv_bfloat16* __restrict__ out,
                                  int R, int C, int mode)
{
    int total = R * C;
    for (int idx = blockIdx.x * blockDim.x + threadIdx.x; idx < total;
         idx += gridDim.x * blockDim.x) {
        int r = idx / C, c = idx - r * C;
        float v = in[idx];
        __nv_bfloat16 hi = __float2bfloat16(v);
        __nv_bfloat16 lo = __float2bfloat16(v - __bfloat162float(hi));
        size_t base = (size_t)r * 3 * C;
        out[base + c]         = hi;
        out[base + C + c]     = mode ? lo : hi;
        out[base + 2 * C + c] = mode ? hi : lo;
    }
}

// Transpose + B-pattern pack: in[R x C] fp32 -> out[C x 3R] bf16 (hi|lo|hi)
__global__ void transpose_pack_kernel(const float* __restrict__ in,
                                      __nv_bfloat16* __restrict__ out,
                                      int R, int C)
{
    __shared__ float t[32][33];
    int rb = blockIdx.y * 32;
    int cb = blockIdx.x * 32;
    int tx = threadIdx.x;
    int ty0 = threadIdx.y;
#pragma unroll
    for (int p = 0; p < 4; p++) {
        int ty = ty0 + p * 8;
        t[ty][tx] = in[(size_t)(rb + ty) * C + cb + tx];
    }
    __syncthreads();
#pragma unroll
    for (int p = 0; p < 4; p++) {
        int ty = ty0 + p * 8;
        float v = t[tx][ty];
        __nv_bfloat16 hi = __float2bfloat16(v);
        __nv_bfloat16 lo = __float2bfloat16(v - __bfloat162float(hi));
        size_t base = (size_t)(cb + ty) * 3 * R;
        out[base + rb + tx]         = hi;
        out[base + R + rb + tx]     = lo;
        out[base + 2 * R + rb + tx] = hi;
    }
}

// ============================================================
__global__ void build_bits_kernel(const float* __restrict__ A, unsigned* __restrict__ bits)
{
    int i = blockIdx.x;
    int w = threadIdx.x;
    const float* row = A + (size_t)i * NN + w * 32;
    unsigned v = 0;
#pragma unroll
    for (int b = 0; b < 32; b++)
        if (row[b] != 0.0f) v |= (1u << b);
    bits[i * WRDS + w] = v;
}

// ============================================================
__global__ void src_dst_kernel(const float* __restrict__ Wh, const float* __restrict__ r,
                               float* __restrict__ src, float* __restrict__ dst)
{
    int warp = (blockIdx.x * blockDim.x + threadIdx.x) >> 5;
    int lane = threadIdx.x & 31;
    if (warp >= NN) return;
    const float* row = Wh + (size_t)warp * FF;
    float a = 0.f, b = 0.f;
    for (int f = lane; f < FF; f += 32) {
        float v = row[f];
        a = fmaf(v, r[f], a);
        b = fmaf(v, r[FF + f], b);
    }
#pragma unroll
    for (int s = 16; s > 0; s >>= 1) {
        a += __shfl_xor_sync(0xffffffffu, a, s);
        b += __shfl_xor_sync(0xffffffffu, b, s);
    }
    if (lane == 0) { src[warp] = a; dst[warp] = b; }
}

// ============================================================
// Short-distance attention (sparse), fused softmax + SpMM + gelu
// ============================================================
__global__ void __launch_bounds__(256) short_attn_kernel(
    const float* __restrict__ A, const float* __restrict__ Wh,
    const float* __restrict__ src, const float* __restrict__ dst,
    float* __restrict__ hk)
{
    __shared__ int   s_idx[NN];
    __shared__ float s_w[NN];
    __shared__ int   s_scan[256];
    __shared__ float s_red[256];

    const int i   = blockIdx.x;
    const int tid = threadIdx.x;
    const float* Arow = A + (size_t)i * NN;

    const int base = tid * 16;
    unsigned m16 = 0; int c = 0;
#pragma unroll
    for (int q = 0; q < 16; q++)
        if (Arow[base + q] != 0.0f) { m16 |= (1u << q); c++; }
    s_scan[tid] = c;
    __syncthreads();
#pragma unroll
    for (int s = 1; s < 256; s <<= 1) {
        int v = (tid >= s) ? s_scan[tid - s] : 0;
        __syncthreads();
        s_scan[tid] += v;
        __syncthreads();
    }
    int start = s_scan[tid] - c;
    int cnt   = s_scan[255];
    {
        int p = start;
#pragma unroll
        for (int q = 0; q < 16; q++)
            if ((m16 >> q) & 1u) s_idx[p++] = base + q;
    }
    __syncthreads();

    float si = src[i];
    float lmax = -FLT_MAX;
    for (int p = tid; p < cnt; p += 256) {
        float e = si + dst[s_idx[p]];
        e = (e > 0.f) ? e : 0.2f * e;
        s_w[p] = e;
        lmax = fmaxf(lmax, e);
    }
    s_red[tid] = lmax;
    __syncthreads();
#pragma unroll
    for (int s = 128; s > 0; s >>= 1) {
        if (tid < s) s_red[tid] = fmaxf(s_red[tid], s_red[tid + s]);
        __syncthreads();
    }
    float mx = s_red[0];
    __syncthreads();

    float lsum = 0.f;
    for (int p = tid; p < cnt; p += 256) {
        float w = expf(s_w[p] - mx);
        s_w[p] = w;
        lsum += w;
    }
    s_red[tid] = lsum;
    __syncthreads();
#pragma unroll
    for (int s = 128; s > 0; s >>= 1) {
        if (tid < s) s_red[tid] += s_red[tid + s];
        __syncthreads();
    }
    float inv = 1.0f / s_red[0];
    __syncthreads();

    float a0 = 0.f, a1 = 0.f;
    for (int p = 0; p < cnt; p++) {
        float w = s_w[p];
        const float* whr = Wh + (size_t)s_idx[p] * FF;
        a0 = fmaf(w, whr[tid],       a0);
        a1 = fmaf(w, whr[tid + 256], a1);
    }
    hk[(size_t)i * FF + tid]       = gelu_tanh(a0 * inv);
    hk[(size_t)i * FF + tid + 256] = gelu_tanh(a1 * inv);
}

// ============================================================
__global__ void hop_step_kernel(const unsigned* __restrict__ Abits,
                                const unsigned* __restrict__ src,
                                unsigned* __restrict__ dst,
                                int iter, const int* __restrict__ num_hops)
{
    __shared__ unsigned s_row[WRDS];
    const int i = blockIdx.x;
    const int t = threadIdx.x;
    s_row[t] = Abits[i * WRDS + t];
    __syncthreads();

    if (iter >= (*num_hops) - 1) {
        dst[i * WRDS + t] = src[i * WRDS + t];
        return;
    }
    unsigned acc = 0;
    for (int w = 0; w < WRDS; w++) {
        unsigned bits = s_row[w];
        while (bits) {
            int b = __ffs(bits) - 1;
            bits &= bits - 1;
            acc |= src[(size_t)(w * 32 + b) * WRDS + t];
        }
    }
    dst[i * WRDS + t] = acc;
}

// ============================================================
// Row softmax (4096-wide) fused with A-pattern bf16 packing
// ============================================================
__global__ void __launch_bounds__(256) softmax_pack_kernel(
    const float* __restrict__ S, __nv_bfloat16* __restrict__ attP)
{
    __shared__ float s_red[256];
    const int i   = blockIdx.x;
    const int tid = threadIdx.x;
    const float* row = S + (size_t)i * NN;
    __nv_bfloat16* orow = attP + (size_t)i * K3N;

    float vals[16];
    float lmax = -FLT_MAX;
#pragma unroll
    for (int p = 0; p < 16; p++) {
        vals[p] = row[tid + p * 256];
        lmax = fmaxf(lmax, vals[p]);
    }
    s_red[tid] = lmax;
    __syncthreads();
#pragma unroll
    for (int s = 128; s > 0; s >>= 1) {
        if (tid < s) s_red[tid] = fmaxf(s_red[tid], s_red[tid + s]);
        __syncthreads();
    }
    float mx = s_red[0];
    __syncthreads();

    float lsum = 0.f;
#pragma unroll
    for (int p = 0; p < 16; p++) {
        float w = expf(vals[p] - mx);
        vals[p] = w;
        lsum += w;
    }
    s_red[tid] = lsum;
    __syncthreads();
#pragma unroll
    for (int s = 128; s > 0; s >>= 1) {
        if (tid < s) s_red[tid] += s_red[tid + s];
        __syncthreads();
    }
    float inv = 1.0f / s_red[0];
#pragma unroll
    for (int p = 0; p < 16; p++) {
        int j = tid + p * 256;
        float a = vals[p] * inv;
        __nv_bfloat16 hi = __float2bfloat16(a);
        __nv_bfloat16 lo = __float2bfloat16(a - __bfloat162float(hi));
        orow[j]            = hi;
        orow[NN + j]       = hi;
        orow[2 * NN + j]   = lo;
    }
}

// ============================================================
// out = sum of 8 partials  (4096 x 512 fp32)
// ============================================================
__global__ void reduce8_kernel(const float* __restrict__ part, float* __restrict__ out)
{
    int total = NN * FF / 4;
    const size_t stride = (size_t)NN * FF / 4;
    for (int idx = blockIdx.x * blockDim.x + threadIdx.x; idx < total;
         idx += gridDim.x * blockDim.x) {
        float4 o = make_float4(0.f, 0.f, 0.f, 0.f);
#pragma unroll
        for (int s = 0; s < NSPLIT; s++) {
            float4 a = reinterpret_cast<const float4*>(part)[idx + s * stride];
            o.x += a.x; o.y += a.y; o.z += a.z; o.w += a.w;
        }
        reinterpret_cast<float4*>(out)[idx] = o;
    }
}

// ============================================================
// Host launch
// ============================================================
extern "C" void kernel_launch(void* const* d_in, const int* in_sizes, int n_in,
                              void* d_out, int out_size)
{
    const float* X  = (const float*)d_in[0];
    const float* A  = (const float*)d_in[1];
    const float* Ws = (const float*)d_in[2];
    const float* r  = (const float*)d_in[3];
    const float* Wl = (const float*)d_in[4];
    const int*   nh = (const int*)d_in[5];
    float* out = (float*)d_out;

    float *Wh, *Wa, *hk, *src, *dst, *S, *part;
    unsigned *Abits, *P, *Q;
    __nv_bfloat16 *Xp, *WsP, *WlP, *hkP, *WaP, *hkTP, *attP;
    cudaGetSymbolAddress((void**)&Wh,    g_Wh);
    cudaGetSymbolAddress((void**)&Wa,    g_Wa);
    cudaGetSymbolAddress((void**)&hk,    g_hk);
    cudaGetSymbolAddress((void**)&src,   g_src);
    cudaGetSymbolAddress((void**)&dst,   g_dst);
    cudaGetSymbolAddress((void**)&S,     g_S);
    cudaGetSymbolAddress((void**)&Abits, g_Abits);
    cudaGetSymbolAddress((void**)&P,     g_P);
    cudaGetSymbolAddress((void**)&Q,     g_Q);
    cudaGetSymbolAddress((void**)&Xp,    g_Xp);
    cudaGetSymbolAddress((void**)&WsP,   g_WsP);
    cudaGetSymbolAddress((void**)&WlP,   g_WlP);
    cudaGetSymbolAddress((void**)&hkP,   g_hkP);
    cudaGetSymbolAddress((void**)&WaP,   g_WaP);
    cudaGetSymbolAddress((void**)&hkTP,  g_hkTP);
    cudaGetSymbolAddress((void**)&attP,  g_attP);
    cudaGetSymbolAddress((void**)&part,  g_part);

    const int smemBytes = NSTG * 2 * 128 * SSTR * 2;   // 73728
    cudaFuncSetAttribute(mma_gemm_nt<false, false, true>,
                         cudaFuncAttributeMaxDynamicSharedMemorySize, smemBytes);
    cudaFuncSetAttribute(mma_gemm_nt<true, false, false>,
                         cudaFuncAttributeMaxDynamicSharedMemorySize, smemBytes);
    cudaFuncSetAttribute(mma_gemm_nt<false, true, false>,
                         cudaFuncAttributeMaxDynamicSharedMemorySize, smemBytes);

    // pack inputs to split-bf16
    pack_split_kernel<<<1024, 256>>>(X,  Xp,  NN, FF, 0);
    pack_split_kernel<<<256,  256>>>(Ws, WsP, FF, FF, 1);
    pack_split_kernel<<<256,  256>>>(Wl, WlP, FF, FF, 1);

    // Wh = X Ws^T and Wa = X Wl^T in ONE dual launch
    mma_gemm_nt<false, false, true><<<dim3(FF / 128, NN / 128, 2), 128, smemBytes>>>(
        Xp, WsP, WlP, Wh, Wa, NN, FF, K3S, K3S, nullptr);

    // adjacency bitset + src/dst + short attention -> hk
    build_bits_kernel<<<NN, WRDS>>>(A, Abits);
    src_dst_kernel<<<NN / 8, 256>>>(Wh, r, src, dst);
    short_attn_kernel<<<NN, 256>>>(A, Wh, src, dst, hk);

    // pack hk (A-pattern), Wa (B-pattern), hk^T (B-pattern)
    pack_split_kernel<<<1024, 256>>>(hk, hkP, NN, FF, 0);
    pack_split_kernel<<<1024, 256>>>(Wa, WaP, NN, FF, 1);
    transpose_pack_kernel<<<dim3(FF / 32, NN / 32), dim3(32, 8)>>>(hk, hkTP, NN, FF);

    // multi-hop reachability (boolean), guarded launches; result in Q
    hop_step_kernel<<<NN, WRDS>>>(Abits, Abits, P, 0, nh);
    hop_step_kernel<<<NN, WRDS>>>(Abits, P, Q, 1, nh);
    hop_step_kernel<<<NN, WRDS>>>(Abits, Q, P, 2, nh);
    hop_step_kernel<<<NN, WRDS>>>(Abits, P, Q, 3, nh);
    hop_step_kernel<<<NN, WRDS>>>(Abits, Q, P, 4, nh);
    hop_step_kernel<<<NN, WRDS>>>(Abits, P, Q, 5, nh);

    // scores = hk Wa^T with reach mask -> S (fp32)
    mma_gemm_nt<true, false, false><<<dim3(NN / 128, NN / 128), 128, smemBytes>>>(
        hkP, WaP, nullptr, S, nullptr, NN, NN, K3S, K3S, Q);

    // softmax + pack att to split-bf16 (A-pattern)
    softmax_pack_kernel<<<NN, 256>>>(S, attP);

    // ok = att2 hk  (split-K = 8, single launch) + reduce
    mma_gemm_nt<false, true, false><<<dim3(FF / 128, NN / 128, NSPLIT), 128, smemBytes>>>(
        attP, hkTP, nullptr, part, nullptr, NN, FF, K3N, K3N / NSPLIT, nullptr);
    reduce8_kernel<<<1024, 256>>>(part, out);
}

// round 8
// speedup vs baseline: 2.9236x; 1.1650x over previous
#include <cuda_runtime.h>
#include <cuda_bf16.h>
#include <float.h>
#include <stdint.h>

// Problem dims (fixed by setup_inputs)
#define NN   4096
#define FF   512
#define WRDS (NN / 32)
#define K3S  (3 * FF)      // 1536  packed K for feature-dim GEMMs
#define K3N  (3 * NN)      // 12288 logical K for the att@hk GEMM
#define KATT 8192          // physical att row stride: [hi(4096) | lo(4096)]
#define NSPLIT 8

// ---------------- device scratch (no allocations allowed) ----------------
__device__ float         g_Wh[NN * FF];
__device__ float         g_Wa[NN * FF];
__device__ float         g_hk[NN * FF];
__device__ float         g_src[NN];
__device__ float         g_dst[NN];
__device__ unsigned      g_Abits[NN * WRDS];
__device__ unsigned      g_P[NN * WRDS];
__device__ unsigned      g_Q[NN * WRDS];
__device__ float         g_S[(size_t)NN * NN];          // 64 MB scores
__device__ __nv_bfloat16 g_Xp [(size_t)NN * K3S];
__device__ __nv_bfloat16 g_WsP[(size_t)FF * K3S];
__device__ __nv_bfloat16 g_WlP[(size_t)FF * K3S];
__device__ __nv_bfloat16 g_hkP[(size_t)NN * K3S];
__device__ __nv_bfloat16 g_WaP[(size_t)NN * K3S];
__device__ __nv_bfloat16 g_hkTP[(size_t)FF * K3N];
__device__ __nv_bfloat16 g_attP[(size_t)NN * KATT];     // 64 MB [hi|lo]
__device__ float         g_part[NSPLIT][(size_t)NN * FF]; // 64 MB split-K partials

// ---------------- helpers ----------------
__device__ __forceinline__ float gelu_tanh(float x) {
    float x3 = x * x * x;
    return 0.5f * x * (1.0f + tanhf(0.7978845608028654f * (x + 0.044715f * x3)));
}
__device__ __forceinline__ uint32_t smem_u32(const void* p) {
    return (uint32_t)__cvta_generic_to_shared(p);
}

// ============================================================
// Tensor-core bf16 NT GEMM: C[M,N] = A[M,Kslice] * B[N,Kslice]^T
// CTA 128x128, 4 warps (2x2), warp tile 64x64, BK=64, 2-stage cp.async.
// DUAL:   blockIdx.z selects (B,C) vs (B2,C2)
// SPLITK: blockIdx.z selects K slice; C += z*M*N
// MASKED: reach-mask epilogue (masked -> -FLT_MAX)
// REMAP:  A-side logical k>=4096 reads physical k-4096 (hi-plane reuse)
// strideA: physical A row stride (== K unless REMAP)
// ============================================================
#define BK     64
#define SSTR   72            // padded halfs per row (144B, 16B multiple)
#define NSTG   2

template <bool MASKED, bool SPLITK, bool DUAL, bool REMAP>
__global__ void __launch_bounds__(128, 3) mma_gemm_nt(
    const __nv_bfloat16* __restrict__ A,
    const __nv_bfloat16* __restrict__ B,
    const __nv_bfloat16* __restrict__ B2,
    float* __restrict__ C,
    float* __restrict__ C2,
    int M, int N, int K, int kSlice, int strideA,
    const unsigned* __restrict__ maskbits)
{
    extern __shared__ __align__(16) unsigned char smem_raw[];
    __nv_bfloat16* AsBase = (__nv_bfloat16*)smem_raw;                 // [NSTG][128][SSTR]
    __nv_bfloat16* BsBase = AsBase + NSTG * 128 * SSTR;

    const int tid  = threadIdx.x;
    const int bx   = blockIdx.x;    // N tile
    const int by   = blockIdx.y;    // M tile
    const int bz   = blockIdx.z;
    const int warp = tid >> 5;
    const int lane = tid & 31;
    const int wm   = (warp >> 1) * 64;
    const int wn   = (warp & 1) * 64;

    const __nv_bfloat16* Bsel = (DUAL && bz) ? B2 : B;
    float* Csel = (DUAL && bz) ? C2 : C;
    int kBegin = 0, kLen = K;
    if (SPLITK) { kBegin = bz * kSlice; kLen = kSlice; Csel = C + (size_t)bz * M * N; }

    const __nv_bfloat16* Arow = A    + (size_t)(by * 128) * strideA;
    const __nv_bfloat16* Bg   = Bsel + (size_t)(bx * 128) * K + kBegin;

    float acc[4][8][4];
#pragma unroll
    for (int mi = 0; mi < 4; mi++)
#pragma unroll
        for (int nj = 0; nj < 8; nj++)
#pragma unroll
            for (int q = 0; q < 4; q++) acc[mi][nj][q] = 0.0f;

    const int nK = kLen / BK;   // BK=64 chunks

    auto load_stage = [&](int s, int kc) {
        __nv_bfloat16* As = AsBase + s * 128 * SSTR;
        __nv_bfloat16* Bs = BsBase + s * 128 * SSTR;
        int colL = kBegin + kc * BK;                    // logical A column
        int colP = REMAP ? (colL < NN ? colL : colL - NN) : colL;
#pragma unroll
        for (int j = 0; j < 8; j++) {
            int idx = tid + j * 128;        // 1024 chunks of 16B per matrix
            int row = idx >> 3;             // 0..127
            int c   = idx & 7;              // 16B chunk within 128B row
            uint32_t sa = smem_u32(&As[row * SSTR + c * 8]);
            const void* ga = Arow + (size_t)row * strideA + colP + c * 8;
            asm volatile("cp.async.cg.shared.global [%0], [%1], 16;" :: "r"(sa), "l"(ga));
            uint32_t sb = smem_u32(&Bs[row * SSTR + c * 8]);
            const void* gb = Bg + (size_t)row * K + kc * BK + c * 8;
            asm volatile("cp.async.cg.shared.global [%0], [%1], 16;" :: "r"(sb), "l"(gb));
        }
    };

    load_stage(0, 0);
    asm volatile("cp.async.commit_group;");

    for (int kc = 0; kc < nK; kc++) {
        const int s = kc & 1;
        if (kc + 1 < nK) {
            load_stage(s ^ 1, kc + 1);
            asm volatile("cp.async.commit_group;");
            asm volatile("cp.async.wait_group 1;");
        } else {
            asm volatile("cp.async.wait_group 0;");
        }
        __syncthreads();

        const __nv_bfloat16* As = AsBase + s * 128 * SSTR;
        const __nv_bfloat16* Bs = BsBase + s * 128 * SSTR;

#pragma unroll
        for (int kk = 0; kk < BK; kk += 16) {
            uint32_t a[4][4];
#pragma unroll
            for (int mi = 0; mi < 4; mi++) {
                int row = wm + mi * 16 + (lane & 7) + ((lane >> 3) & 1) * 8;
                int col = kk + (lane >> 4) * 8;
                uint32_t addr = smem_u32(&As[row * SSTR + col]);
                asm volatile("ldmatrix.sync.aligned.m8n8.x4.shared.b16 {%0,%1,%2,%3},[%4];"
                    : "=r"(a[mi][0]), "=r"(a[mi][1]), "=r"(a[mi][2]), "=r"(a[mi][3])
                    : "r"(addr));
            }
            uint32_t b[8][2];
#pragma unroll
            for (int nj4 = 0; nj4 < 4; nj4++) {
                int row = wn + nj4 * 16 + (lane & 7) + (lane >> 4) * 8;
                int col = kk + ((lane >> 3) & 1) * 8;
                uint32_t addr = smem_u32(&Bs[row * SSTR + col]);
                asm volatile("ldmatrix.sync.aligned.m8n8.x4.shared.b16 {%0,%1,%2,%3},[%4];"
                    : "=r"(b[nj4 * 2][0]), "=r"(b[nj4 * 2][1]),
                      "=r"(b[nj4 * 2 + 1][0]), "=r"(b[nj4 * 2 + 1][1])
                    : "r"(addr));
            }
#pragma unroll
            for (int mi = 0; mi < 4; mi++)
#pragma unroll
                for (int nj = 0; nj < 8; nj++)
                    asm volatile(
                        "mma.sync.aligned.m16n8k16.row.col.f32.bf16.bf16.f32 "
                        "{%0,%1,%2,%3},{%4,%5,%6,%7},{%8,%9},{%0,%1,%2,%3};"
                        : "+f"(acc[mi][nj][0]), "+f"(acc[mi][nj][1]),
                          "+f"(acc[mi][nj][2]), "+f"(acc[mi][nj][3])
                        : "r"(a[mi][0]), "r"(a[mi][1]), "r"(a[mi][2]), "r"(a[mi][3]),
                          "r"(b[nj][0]), "r"(b[nj][1]));
        }
        __syncthreads();
    }

    // epilogue
    const int g = lane >> 2;
    const int c = lane & 3;
#pragma unroll
    for (int mi = 0; mi < 4; mi++) {
#pragma unroll
        for (int nj = 0; nj < 8; nj++) {
            int row0 = by * 128 + wm + mi * 16 + g;
            int row1 = row0 + 8;
            int col  = bx * 128 + wn + nj * 8 + c * 2;
            float v0 = acc[mi][nj][0], v1 = acc[mi][nj][1];
            float v2 = acc[mi][nj][2], v3 = acc[mi][nj][3];
            if (MASKED) {
                unsigned w0 = maskbits[(size_t)row0 * (N / 32) + (col >> 5)];
                unsigned w1 = maskbits[(size_t)row1 * (N / 32) + (col >> 5)];
                if (!((w0 >> (col & 31)) & 1u))       v0 = -FLT_MAX;
                if (!((w0 >> ((col + 1) & 31)) & 1u)) v1 = -FLT_MAX;
                if (!((w1 >> (col & 31)) & 1u))       v2 = -FLT_MAX;
                if (!((w1 >> ((col + 1) & 31)) & 1u)) v3 = -FLT_MAX;
            }
            *reinterpret_cast<float2*>(&Csel[(size_t)row0 * N + col]) = make_float2(v0, v1);
            *reinterpret_cast<float2*>(&Csel[(size_t)row1 * N + col]) = make_float2(v2, v3);
        }
    }
}

// ============================================================
// fp32 -> split bf16 packing. mode 0: [hi|hi|lo], mode 1: [hi|lo|hi]
// ============================================================
__global__ void pack_split_kernel(const float* __restrict__ in,
                                  __nv_bfloat16* __restrict__ out,
                                  int R, int C, int mode)
{
    int total = R * C;
    for (int idx = blockIdx.x * blockDim.x + threadIdx.x; idx < total;
         idx += gridDim.x * blockDim.x) {
        int r = idx / C, c = idx - r * C;
        float v = in[idx];
        __nv_bfloat16 hi = __float2bfloat16(v);
        __nv_bfloat16 lo = __float2bfloat16(v - __bfloat162float(hi));
        size_t base = (size_t)r * 3 * C;
        out[base + c]         = hi;
        out[base + C + c]     = mode ? lo : hi;
        out[base + 2 * C + c] = mode ? hi : lo;
    }
}

// Transpose + B-pattern pack: in[R x C] fp32 -> out[C x 3R] bf16 (hi|lo|hi)
__global__ void transpose_pack_kernel(const float* __restrict__ in,
                                      __nv_bfloat16* __restrict__ out,
                                      int R, int C)
{
    __shared__ float t[32][33];
    int rb = blockIdx.y * 32;
    int cb = blockIdx.x * 32;
    int tx = threadIdx.x;
    int ty0 = threadIdx.y;
#pragma unroll
    for (int p = 0; p < 4; p++) {
        int ty = ty0 + p * 8;
        t[ty][tx] = in[(size_t)(rb + ty) * C + cb + tx];
    }
    __syncthreads();
#pragma unroll
    for (int p = 0; p < 4; p++) {
        int ty = ty0 + p * 8;
        float v = t[tx][ty];
        __nv_bfloat16 hi = __float2bfloat16(v);
        __nv_bfloat16 lo = __float2bfloat16(v - __bfloat162float(hi));
        size_t base = (size_t)(cb + ty) * 3 * R;
        out[base + rb + tx]         = hi;
        out[base + R + rb + tx]     = lo;
        out[base + 2 * R + rb + tx] = hi;
    }
}

// ============================================================
__global__ void src_dst_kernel(const float* __restrict__ Wh, const float* __restrict__ r,
                               float* __restrict__ src, float* __restrict__ dst)
{
    int warp = (blockIdx.x * blockDim.x + threadIdx.x) >> 5;
    int lane = threadIdx.x & 31;
    if (warp >= NN) return;
    const float* row = Wh + (size_t)warp * FF;
    float a = 0.f, b = 0.f;
    for (int f = lane; f < FF; f += 32) {
        float v = row[f];
        a = fmaf(v, r[f], a);
        b = fmaf(v, r[FF + f], b);
    }
#pragma unroll
    for (int s = 16; s > 0; s >>= 1) {
        a += __shfl_xor_sync(0xffffffffu, a, s);
        b += __shfl_xor_sync(0xffffffffu, b, s);
    }
    if (lane == 0) { src[warp] = a; dst[warp] = b; }
}

// ============================================================
// Short-distance attention (sparse), fused softmax + SpMM + gelu.
// Also emits the bit-packed adjacency row (fused, saves a 64MB re-read).
// ============================================================
__global__ void __launch_bounds__(256) short_attn_kernel(
    const float* __restrict__ A, const float* __restrict__ Wh,
    const float* __restrict__ src, const float* __restrict__ dst,
    float* __restrict__ hk, unsigned* __restrict__ bits)
{
    __shared__ int      s_idx[NN];
    __shared__ float    s_w[NN];
    __shared__ int      s_scan[256];
    __shared__ float    s_red[256];
    __shared__ unsigned s_m16[256];

    const int i   = blockIdx.x;
    const int tid = threadIdx.x;
    const float* Arow = A + (size_t)i * NN;

    const int base = tid * 16;
    unsigned m16 = 0; int c = 0;
#pragma unroll
    for (int q = 0; q < 16; q++)
        if (Arow[base + q] != 0.0f) { m16 |= (1u << q); c++; }
    s_m16[tid] = m16;
    s_scan[tid] = c;
    __syncthreads();
    // fused adjacency bitset output (one 32-bit word per 2 threads)
    if (tid < WRDS)
        bits[(size_t)i * WRDS + tid] = s_m16[2 * tid] | (s_m16[2 * tid + 1] << 16);
#pragma unroll
    for (int s = 1; s < 256; s <<= 1) {
        int v = (tid >= s) ? s_scan[tid - s] : 0;
        __syncthreads();
        s_scan[tid] += v;
        __syncthreads();
    }
    int start = s_scan[tid] - c;
    int cnt   = s_scan[255];
    {
        int p = start;
#pragma unroll
        for (int q = 0; q < 16; q++)
            if ((m16 >> q) & 1u) s_idx[p++] = base + q;
    }
    __syncthreads();

    float si = src[i];
    float lmax = -FLT_MAX;
    for (int p = tid; p < cnt; p += 256) {
        float e = si + dst[s_idx[p]];
        e = (e > 0.f) ? e : 0.2f * e;
        s_w[p] = e;
        lmax = fmaxf(lmax, e);
    }
    s_red[tid] = lmax;
    __syncthreads();
#pragma unroll
    for (int s = 128; s > 0; s >>= 1) {
        if (tid < s) s_red[tid] = fmaxf(s_red[tid], s_red[tid + s]);
        __syncthreads();
    }
    float mx = s_red[0];
    __syncthreads();

    float lsum = 0.f;
    for (int p = tid; p < cnt; p += 256) {
        float w = expf(s_w[p] - mx);
        s_w[p] = w;
        lsum += w;
    }
    s_red[tid] = lsum;
    __syncthreads();
#pragma unroll
    for (int s = 128; s > 0; s >>= 1) {
        if (tid < s) s_red[tid] += s_red[tid + s];
        __syncthreads();
    }
    float inv = 1.0f / s_red[0];
    __syncthreads();

    float a0 = 0.f, a1 = 0.f;
    for (int p = 0; p < cnt; p++) {
        float w = s_w[p];
        const float* whr = Wh + (size_t)s_idx[p] * FF;
        a0 = fmaf(w, whr[tid],       a0);
        a1 = fmaf(w, whr[tid + 256], a1);
    }
    hk[(size_t)i * FF + tid]       = gelu_tanh(a0 * inv);
    hk[(size_t)i * FF + tid + 256] = gelu_tanh(a1 * inv);
}

// ============================================================
__global__ void hop_step_kernel(const unsigned* __restrict__ Abits,
                                const unsigned* __restrict__ src,
                                unsigned* __restrict__ dst,
                                int iter, const int* __restrict__ num_hops)
{
    __shared__ unsigned s_row[WRDS];
    const int i = blockIdx.x;
    const int t = threadIdx.x;
    s_row[t] = Abits[i * WRDS + t];
    __syncthreads();

    if (iter >= (*num_hops) - 1) {
        dst[i * WRDS + t] = src[i * WRDS + t];
        return;
    }
    unsigned acc = 0;
    for (int w = 0; w < WRDS; w++) {
        unsigned bits = s_row[w];
        while (bits) {
            int b = __ffs(bits) - 1;
            bits &= bits - 1;
            acc |= src[(size_t)(w * 32 + b) * WRDS + t];
        }
    }
    dst[i * WRDS + t] = acc;
}

// ============================================================
// Row softmax (4096-wide) fused with [hi|lo] bf16 packing (stride 8192)
// ============================================================
__global__ void __launch_bounds__(256) softmax_pack_kernel(
    const float* __restrict__ S, __nv_bfloat16* __restrict__ attP)
{
    __shared__ float s_red[256];
    const int i   = blockIdx.x;
    const int tid = threadIdx.x;
    const float* row = S + (size_t)i * NN;
    __nv_bfloat16* orow = attP + (size_t)i * KATT;

    float vals[16];
    float lmax = -FLT_MAX;
#pragma unroll
    for (int p = 0; p < 16; p++) {
        vals[p] = row[tid + p * 256];
        lmax = fmaxf(lmax, vals[p]);
    }
    s_red[tid] = lmax;
    __syncthreads();
#pragma unroll
    for (int s = 128; s > 0; s >>= 1) {
        if (tid < s) s_red[tid] = fmaxf(s_red[tid], s_red[tid + s]);
        __syncthreads();
    }
    float mx = s_red[0];
    __syncthreads();

    float lsum = 0.f;
#pragma unroll
    for (int p = 0; p < 16; p++) {
        float w = expf(vals[p] - mx);
        vals[p] = w;
        lsum += w;
    }
    s_red[tid] = lsum;
    __syncthreads();
#pragma unroll
    for (int s = 128; s > 0; s >>= 1) {
        if (tid < s) s_red[tid] += s_red[tid + s];
        __syncthreads();
    }
    float inv = 1.0f / s_red[0];
#pragma unroll
    for (int p = 0; p < 16; p++) {
        int j = tid + p * 256;
        float a = vals[p] * inv;
        __nv_bfloat16 hi = __float2bfloat16(a);
        __nv_bfloat16 lo = __float2bfloat16(a - __bfloat162float(hi));
        orow[j]      = hi;
        orow[NN + j] = lo;
    }
}

// ============================================================
// out = sum of 8 partials  (4096 x 512 fp32)
// ============================================================
__global__ void reduce8_kernel(const float* __restrict__ part, float* __restrict__ out)
{
    int total = NN * FF / 4;
    const size_t stride = (size_t)NN * FF / 4;
    for (int idx = blockIdx.x * blockDim.x + threadIdx.x; idx < total;
         idx += gridDim.x * blockDim.x) {
        float4 o = make_float4(0.f, 0.f, 0.f, 0.f);
#pragma unroll
        for (int s = 0; s < NSPLIT; s++) {
            float4 a = reinterpret_cast<const float4*>(part)[idx + s * stride];
            o.x += a.x; o.y += a.y; o.z += a.z; o.w += a.w;
        }
        reinterpret_cast<float4*>(out)[idx] = o;
    }
}

// ============================================================
// Host launch
// ============================================================
extern "C" void kernel_launch(void* const* d_in, const int* in_sizes, int n_in,
                              void* d_out, int out_size)
{
    const float* X  = (const float*)d_in[0];
    const float* A  = (const float*)d_in[1];
    const float* Ws = (const float*)d_in[2];
    const float* r  = (const float*)d_in[3];
    const float* Wl = (const float*)d_in[4];
    const int*   nh = (const int*)d_in[5];
    float* out = (float*)d_out;

    float *Wh, *Wa, *hk, *src, *dst, *S, *part;
    unsigned *Abits, *P, *Q;
    __nv_bfloat16 *Xp, *WsP, *WlP, *hkP, *WaP, *hkTP, *attP;
    cudaGetSymbolAddress((void**)&Wh,    g_Wh);
    cudaGetSymbolAddress((void**)&Wa,    g_Wa);
    cudaGetSymbolAddress((void**)&hk,    g_hk);
    cudaGetSymbolAddress((void**)&src,   g_src);
    cudaGetSymbolAddress((void**)&dst,   g_dst);
    cudaGetSymbolAddress((void**)&S,     g_S);
    cudaGetSymbolAddress((void**)&Abits, g_Abits);
    cudaGetSymbolAddress((void**)&P,     g_P);
    cudaGetSymbolAddress((void**)&Q,     g_Q);
    cudaGetSymbolAddress((void**)&Xp,    g_Xp);
    cudaGetSymbolAddress((void**)&WsP,   g_WsP);
    cudaGetSymbolAddress((void**)&WlP,   g_WlP);
    cudaGetSymbolAddress((void**)&hkP,   g_hkP);
    cudaGetSymbolAddress((void**)&WaP,   g_WaP);
    cudaGetSymbolAddress((void**)&hkTP,  g_hkTP);
    cudaGetSymbolAddress((void**)&attP,  g_attP);
    cudaGetSymbolAddress((void**)&part,  g_part);

    const int smemBytes = NSTG * 2 * 128 * SSTR * 2;   // 73728
    cudaFuncSetAttribute(mma_gemm_nt<false, false, true, false>,
                         cudaFuncAttributeMaxDynamicSharedMemorySize, smemBytes);
    cudaFuncSetAttribute(mma_gemm_nt<true, false, false, false>,
                         cudaFuncAttributeMaxDynamicSharedMemorySize, smemBytes);
    cudaFuncSetAttribute(mma_gemm_nt<false, true, false, true>,
                         cudaFuncAttributeMaxDynamicSharedMemorySize, smemBytes);

    // pack inputs to split-bf16
    pack_split_kernel<<<1024, 256>>>(X,  Xp,  NN, FF, 0);
    pack_split_kernel<<<256,  256>>>(Ws, WsP, FF, FF, 1);
    pack_split_kernel<<<256,  256>>>(Wl, WlP, FF, FF, 1);

    // Wh = X Ws^T and Wa = X Wl^T in ONE dual launch
    mma_gemm_nt<false, false, true, false><<<dim3(FF / 128, NN / 128, 2), 128, smemBytes>>>(
        Xp, WsP, WlP, Wh, Wa, NN, FF, K3S, K3S, K3S, nullptr);

    // src/dst + short attention (emits Abits too) -> hk
    src_dst_kernel<<<NN / 8, 256>>>(Wh, r, src, dst);
    short_attn_kernel<<<NN, 256>>>(A, Wh, src, dst, hk, Abits);

    // pack hk (A-pattern), Wa (B-pattern), hk^T (B-pattern)
    pack_split_kernel<<<1024, 256>>>(hk, hkP, NN, FF, 0);
    pack_split_kernel<<<1024, 256>>>(Wa, WaP, NN, FF, 1);
    transpose_pack_kernel<<<dim3(FF / 32, NN / 32), dim3(32, 8)>>>(hk, hkTP, NN, FF);

    // multi-hop reachability (boolean), guarded launches; result in Q
    hop_step_kernel<<<NN, WRDS>>>(Abits, Abits, P, 0, nh);
    hop_step_kernel<<<NN, WRDS>>>(Abits, P, Q, 1, nh);
    hop_step_kernel<<<NN, WRDS>>>(Abits, Q, P, 2, nh);
    hop_step_kernel<<<NN, WRDS>>>(Abits, P, Q, 3, nh);
    hop_step_kernel<<<NN, WRDS>>>(Abits, Q, P, 4, nh);
    hop_step_kernel<<<NN, WRDS>>>(Abits, P, Q, 5, nh);

    // scores = hk Wa^T with reach mask -> S (fp32)
    mma_gemm_nt<true, false, false, false><<<dim3(NN / 128, NN / 128), 128, smemBytes>>>(
        hkP, WaP, nullptr, S, nullptr, NN, NN, K3S, K3S, K3S, Q);

    // softmax + pack att to [hi|lo] bf16 (stride 8192)
    softmax_pack_kernel<<<NN, 256>>>(S, attP);

    // ok = att2 hk  (split-K = 8, A-side K-remap over [hi|lo]) + reduce
    mma_gemm_nt<false, true, false, true><<<dim3(FF / 128, NN / 128, NSPLIT), 128, smemBytes>>>(
        attP, hkTP, nullptr, part, nullptr, NN, FF, K3N, K3N / NSPLIT, KATT, nullptr);
    reduce8_kernel<<<1024, 256>>>(part, out);
}